// round 2
// baseline (speedup 1.0000x reference)
#include <cuda_runtime.h>

// ---------------------------------------------------------------------------
// VQ-VAE forward, fp32 SIMT baseline.
// Stages: G1(relu) -> G2 -> VQ argmin -> G3(gather+relu) -> G4(sigmoid)
// ---------------------------------------------------------------------------

#define BZ        16384
#define INPUT_DIM 1024
#define HIDDEN    400
#define EMBED_DIM 256
#define EMBED_NUM 2048

// scratch (allocation-free: __device__ globals)
__device__ float g_h1[BZ * HIDDEN];
__device__ float g_ze[BZ * EMBED_DIM];
__device__ float g_h3[BZ * HIDDEN];
__device__ int   g_idx[BZ];
__device__ float g_enorm[EMBED_NUM];

// ---------------------------------------------------------------------------
// ||e_j||^2 for all codes. warp-per-row.
// ---------------------------------------------------------------------------
__global__ void enorm_kernel(const float* __restrict__ E, float* __restrict__ en) {
    int j    = blockIdx.x * 8 + (threadIdx.x >> 5);
    int lane = threadIdx.x & 31;
    const float* row = E + (long)j * EMBED_DIM;
    float s = 0.f;
    #pragma unroll
    for (int k = lane; k < EMBED_DIM; k += 32) {
        float v = row[k];
        s += v * v;
    }
    #pragma unroll
    for (int o = 16; o; o >>= 1) s += __shfl_xor_sync(0xFFFFFFFFu, s, o);
    if (lane == 0) en[j] = s;
}

// ---------------------------------------------------------------------------
// Generic tiled GEMM: C[M,N] = act(A[M,K] @ B[N,K]^T + bias[N])
// BM=BN=64, BK=16, 256 threads, 4x4 microtile.
// GATHER: A row m is A + gidx[m]*K (emb gather fused into G3).
// ACT: 0 none, 1 relu, 2 sigmoid.
// Requires: M % 64 == 0, K % 16 == 0 (holds for all stages). N arbitrary.
// ---------------------------------------------------------------------------
#define GBM 64
#define GBN 64
#define GBK 16

template <int ACT, bool GATHER>
__global__ __launch_bounds__(256)
void gemm_bias_act(const float* __restrict__ A, const float* __restrict__ B,
                   const float* __restrict__ bias, float* __restrict__ C,
                   int M, int N, int K, const int* __restrict__ gidx = nullptr) {
    __shared__ float As[GBK][GBM];
    __shared__ float Bs[GBK][GBN];

    const int tid = threadIdx.x;
    const int tx  = tid & 15;        // 0..15 (N dir)
    const int ty  = tid >> 4;        // 0..15 (M dir)
    const int m0  = blockIdx.y * GBM;
    const int n0  = blockIdx.x * GBN;

    const int lr = tid >> 2;         // 0..63 row within tile
    const int lc = (tid & 3) * 4;    // 0,4,8,12 col (float4)

    const int am = m0 + lr;
    const float* Aptr;
    if (GATHER) Aptr = A + (long)gidx[am] * K;
    else        Aptr = A + (long)am * K;

    const int   bn   = n0 + lr;
    const bool  bok  = (bn < N);
    const float* Bptr = B + (long)(bok ? bn : 0) * K;

    float acc[4][4];
    #pragma unroll
    for (int i = 0; i < 4; i++)
        #pragma unroll
        for (int j = 0; j < 4; j++) acc[i][j] = 0.f;

    for (int k0 = 0; k0 < K; k0 += GBK) {
        float4 av = *(const float4*)(Aptr + k0 + lc);
        float4 bv = make_float4(0.f, 0.f, 0.f, 0.f);
        if (bok) bv = *(const float4*)(Bptr + k0 + lc);

        As[lc + 0][lr] = av.x; As[lc + 1][lr] = av.y;
        As[lc + 2][lr] = av.z; As[lc + 3][lr] = av.w;
        Bs[lc + 0][lr] = bv.x; Bs[lc + 1][lr] = bv.y;
        Bs[lc + 2][lr] = bv.z; Bs[lc + 3][lr] = bv.w;
        __syncthreads();

        #pragma unroll
        for (int kk = 0; kk < GBK; kk++) {
            float4 a = *(const float4*)&As[kk][ty * 4];
            float4 b = *(const float4*)&Bs[kk][tx * 4];
            float ra[4] = {a.x, a.y, a.z, a.w};
            float rb[4] = {b.x, b.y, b.z, b.w};
            #pragma unroll
            for (int i = 0; i < 4; i++)
                #pragma unroll
                for (int j = 0; j < 4; j++)
                    acc[i][j] = fmaf(ra[i], rb[j], acc[i][j]);
        }
        __syncthreads();
    }

    #pragma unroll
    for (int j = 0; j < 4; j++) {
        int n = n0 + tx * 4 + j;
        if (n >= N) continue;
        float bb = bias[n];
        #pragma unroll
        for (int i = 0; i < 4; i++) {
            float v = acc[i][j] + bb;
            if (ACT == 1) v = fmaxf(v, 0.f);
            if (ACT == 2) v = 1.f / (1.f + __expf(-v));
            C[(long)(m0 + ty * 4 + i) * N + n] = v;
        }
    }
}

// ---------------------------------------------------------------------------
// VQ argmin: for 32 rows per block, stream all 2048 codes.
// score_j = ||e_j||^2 - 2 * <z, e_j>   (||z||^2 dropped: row-constant)
// Z tile (32x256) stays in smem; per-thread 2 rows x 4 cols microtile,
// in-register running argmin; smem tree at the end.
// ---------------------------------------------------------------------------
__global__ __launch_bounds__(256)
void vq_argmin(const float* __restrict__ Z, const float* __restrict__ E,
               const float* __restrict__ enorm, int* __restrict__ idxOut) {
    __shared__ float Zs[32][EMBED_DIM + 1];   // +1 pad: kill bank conflicts
    __shared__ float Es[GBK][64];
    __shared__ float rs[32][16];
    __shared__ int   ri[32][16];

    const int tid = threadIdx.x;
    const int tx  = tid & 15;
    const int ty  = tid >> 4;
    const int m0  = blockIdx.x * 32;

    // stage Z tile: 32 rows x 256 floats = 2048 float4
    for (int t = tid; t < 2048; t += 256) {
        int row = t >> 6;
        int c   = (t & 63) * 4;
        float4 v = *(const float4*)(Z + (long)(m0 + row) * EMBED_DIM + c);
        Zs[row][c + 0] = v.x; Zs[row][c + 1] = v.y;
        Zs[row][c + 2] = v.z; Zs[row][c + 3] = v.w;
    }
    __syncthreads();

    const int lr = tid >> 2;         // 0..63 code row within chunk
    const int lc = (tid & 3) * 4;    // float4 col

    float best[2]  = {3.4e38f, 3.4e38f};
    int   bidx[2]  = {0, 0};

    for (int nc = 0; nc < EMBED_NUM; nc += 64) {
        float acc[2][4];
        #pragma unroll
        for (int i = 0; i < 2; i++)
            #pragma unroll
            for (int j = 0; j < 4; j++) acc[i][j] = 0.f;

        for (int k0 = 0; k0 < EMBED_DIM; k0 += GBK) {
            float4 bv = *(const float4*)(E + (long)(nc + lr) * EMBED_DIM + k0 + lc);
            Es[lc + 0][lr] = bv.x; Es[lc + 1][lr] = bv.y;
            Es[lc + 2][lr] = bv.z; Es[lc + 3][lr] = bv.w;
            __syncthreads();

            #pragma unroll
            for (int kk = 0; kk < GBK; kk++) {
                float a0 = Zs[ty * 2 + 0][k0 + kk];
                float a1 = Zs[ty * 2 + 1][k0 + kk];
                float4 b = *(const float4*)&Es[kk][tx * 4];
                float rb[4] = {b.x, b.y, b.z, b.w};
                #pragma unroll
                for (int j = 0; j < 4; j++) {
                    acc[0][j] = fmaf(a0, rb[j], acc[0][j]);
                    acc[1][j] = fmaf(a1, rb[j], acc[1][j]);
                }
            }
            __syncthreads();
        }

        #pragma unroll
        for (int j = 0; j < 4; j++) {
            int n = nc + tx * 4 + j;
            float en = enorm[n];
            #pragma unroll
            for (int i = 0; i < 2; i++) {
                float s = fmaf(-2.f, acc[i][j], en);
                if (s < best[i]) { best[i] = s; bidx[i] = n; }
            }
        }
    }

    #pragma unroll
    for (int i = 0; i < 2; i++) {
        rs[ty * 2 + i][tx] = best[i];
        ri[ty * 2 + i][tx] = bidx[i];
    }
    __syncthreads();

    if (tid < 32) {
        float b  = 3.4e38f;
        int   bi = 0x7FFFFFFF;
        #pragma unroll
        for (int t = 0; t < 16; t++) {
            float s = rs[tid][t];
            int   ii = ri[tid][t];
            if (s < b || (s == b && ii < bi)) { b = s; bi = ii; }
        }
        idxOut[m0 + tid] = bi;
    }
}

// ---------------------------------------------------------------------------
// launch
// ---------------------------------------------------------------------------
extern "C" void kernel_launch(void* const* d_in, const int* in_sizes, int n_in,
                              void* d_out, int out_size) {
    const float* x   = (const float*)d_in[0];
    const float* W1  = (const float*)d_in[1];
    const float* b1  = (const float*)d_in[2];
    const float* W2  = (const float*)d_in[3];
    const float* b2  = (const float*)d_in[4];
    const float* W3  = (const float*)d_in[5];
    const float* b3  = (const float*)d_in[6];
    const float* W4  = (const float*)d_in[7];
    const float* b4  = (const float*)d_in[8];
    const float* emb = (const float*)d_in[9];
    float* out = (float*)d_out;

    float *h1, *ze, *h3, *en;
    int* idx;
    cudaGetSymbolAddress((void**)&h1, g_h1);
    cudaGetSymbolAddress((void**)&ze, g_ze);
    cudaGetSymbolAddress((void**)&h3, g_h3);
    cudaGetSymbolAddress((void**)&en, g_enorm);
    cudaGetSymbolAddress((void**)&idx, g_idx);

    // ||e_j||^2
    enorm_kernel<<<EMBED_NUM / 8, 256>>>(emb, en);

    // G1: h1 = relu(x @ W1^T + b1)    (16384,400,1024)
    gemm_bias_act<1, false><<<dim3((HIDDEN + 63) / 64, BZ / 64), 256>>>(
        x, W1, b1, h1, BZ, HIDDEN, INPUT_DIM, nullptr);

    // G2: z_e = h1 @ W2^T + b2        (16384,256,400)
    gemm_bias_act<0, false><<<dim3(EMBED_DIM / 64, BZ / 64), 256>>>(
        h1, W2, b2, ze, BZ, EMBED_DIM, HIDDEN, nullptr);

    // VQ: idx = argmin_j ||z_e - e_j||^2
    vq_argmin<<<BZ / 32, 256>>>(ze, emb, en, idx);

    // G3: h3 = relu(emb[idx] @ W3^T + b3)   (16384,400,256) gather fused
    gemm_bias_act<1, true><<<dim3((HIDDEN + 63) / 64, BZ / 64), 256>>>(
        emb, W3, b3, h3, BZ, HIDDEN, EMBED_DIM, idx);

    // G4: out = sigmoid(h3 @ W4^T + b4)     (16384,1024,400)
    gemm_bias_act<2, false><<<dim3(INPUT_DIM / 64, BZ / 64), 256>>>(
        h3, W4, b4, out, BZ, INPUT_DIM, HIDDEN, nullptr);
}

// round 3
// speedup vs baseline: 1.0017x; 1.0017x over previous
#include <cuda_runtime.h>

// ---------------------------------------------------------------------------
// VQ-VAE forward, fp32 SIMT baseline.
// Stages: G1(relu) -> G2 -> VQ argmin -> G3(gather+relu) -> G4(sigmoid)
// ---------------------------------------------------------------------------

#define BZ        16384
#define INPUT_DIM 1024
#define HIDDEN    400
#define EMBED_DIM 256
#define EMBED_NUM 2048

// scratch (allocation-free: __device__ globals)
__device__ float g_h1[BZ * HIDDEN];
__device__ float g_ze[BZ * EMBED_DIM];
__device__ float g_h3[BZ * HIDDEN];
__device__ int   g_idx[BZ];
__device__ float g_enorm[EMBED_NUM];

// ---------------------------------------------------------------------------
// ||e_j||^2 for all codes. warp-per-row.
// ---------------------------------------------------------------------------
__global__ void enorm_kernel(const float* __restrict__ E, float* __restrict__ en) {
    int j    = blockIdx.x * 8 + (threadIdx.x >> 5);
    int lane = threadIdx.x & 31;
    const float* row = E + (long)j * EMBED_DIM;
    float s = 0.f;
    #pragma unroll
    for (int k = lane; k < EMBED_DIM; k += 32) {
        float v = row[k];
        s += v * v;
    }
    #pragma unroll
    for (int o = 16; o; o >>= 1) s += __shfl_xor_sync(0xFFFFFFFFu, s, o);
    if (lane == 0) en[j] = s;
}

// ---------------------------------------------------------------------------
// Generic tiled GEMM: C[M,N] = act(A[M,K] @ B[N,K]^T + bias[N])
// BM=BN=64, BK=16, 256 threads, 4x4 microtile.
// GATHER: A row m is A + gidx[m]*K (emb gather fused into G3).
// ACT: 0 none, 1 relu, 2 sigmoid.
// Requires: M % 64 == 0, K % 16 == 0 (holds for all stages). N arbitrary.
// ---------------------------------------------------------------------------
#define GBM 64
#define GBN 64
#define GBK 16

template <int ACT, bool GATHER>
__global__ __launch_bounds__(256)
void gemm_bias_act(const float* __restrict__ A, const float* __restrict__ B,
                   const float* __restrict__ bias, float* __restrict__ C,
                   int M, int N, int K, const int* __restrict__ gidx = nullptr) {
    __shared__ float As[GBK][GBM];
    __shared__ float Bs[GBK][GBN];

    const int tid = threadIdx.x;
    const int tx  = tid & 15;        // 0..15 (N dir)
    const int ty  = tid >> 4;        // 0..15 (M dir)
    const int m0  = blockIdx.y * GBM;
    const int n0  = blockIdx.x * GBN;

    const int lr = tid >> 2;         // 0..63 row within tile
    const int lc = (tid & 3) * 4;    // 0,4,8,12 col (float4)

    const int am = m0 + lr;
    const float* Aptr;
    if (GATHER) Aptr = A + (long)gidx[am] * K;
    else        Aptr = A + (long)am * K;

    const int   bn   = n0 + lr;
    const bool  bok  = (bn < N);
    const float* Bptr = B + (long)(bok ? bn : 0) * K;

    float acc[4][4];
    #pragma unroll
    for (int i = 0; i < 4; i++)
        #pragma unroll
        for (int j = 0; j < 4; j++) acc[i][j] = 0.f;

    for (int k0 = 0; k0 < K; k0 += GBK) {
        float4 av = *(const float4*)(Aptr + k0 + lc);
        float4 bv = make_float4(0.f, 0.f, 0.f, 0.f);
        if (bok) bv = *(const float4*)(Bptr + k0 + lc);

        As[lc + 0][lr] = av.x; As[lc + 1][lr] = av.y;
        As[lc + 2][lr] = av.z; As[lc + 3][lr] = av.w;
        Bs[lc + 0][lr] = bv.x; Bs[lc + 1][lr] = bv.y;
        Bs[lc + 2][lr] = bv.z; Bs[lc + 3][lr] = bv.w;
        __syncthreads();

        #pragma unroll
        for (int kk = 0; kk < GBK; kk++) {
            float4 a = *(const float4*)&As[kk][ty * 4];
            float4 b = *(const float4*)&Bs[kk][tx * 4];
            float ra[4] = {a.x, a.y, a.z, a.w};
            float rb[4] = {b.x, b.y, b.z, b.w};
            #pragma unroll
            for (int i = 0; i < 4; i++)
                #pragma unroll
                for (int j = 0; j < 4; j++)
                    acc[i][j] = fmaf(ra[i], rb[j], acc[i][j]);
        }
        __syncthreads();
    }

    #pragma unroll
    for (int j = 0; j < 4; j++) {
        int n = n0 + tx * 4 + j;
        if (n >= N) continue;
        float bb = bias[n];
        #pragma unroll
        for (int i = 0; i < 4; i++) {
            float v = acc[i][j] + bb;
            if (ACT == 1) v = fmaxf(v, 0.f);
            if (ACT == 2) v = 1.f / (1.f + __expf(-v));
            C[(long)(m0 + ty * 4 + i) * N + n] = v;
        }
    }
}

// ---------------------------------------------------------------------------
// VQ argmin: for 32 rows per block, stream all 2048 codes.
// score_j = ||e_j||^2 - 2 * <z, e_j>   (||z||^2 dropped: row-constant)
// Z tile (32x256) stays in smem; per-thread 2 rows x 4 cols microtile,
// in-register running argmin; smem tree at the end.
// ---------------------------------------------------------------------------
__global__ __launch_bounds__(256)
void vq_argmin(const float* __restrict__ Z, const float* __restrict__ E,
               const float* __restrict__ enorm, int* __restrict__ idxOut) {
    __shared__ float Zs[32][EMBED_DIM + 1];   // +1 pad: kill bank conflicts
    __shared__ float Es[GBK][64];
    __shared__ float rs[32][16];
    __shared__ int   ri[32][16];

    const int tid = threadIdx.x;
    const int tx  = tid & 15;
    const int ty  = tid >> 4;
    const int m0  = blockIdx.x * 32;

    // stage Z tile: 32 rows x 256 floats = 2048 float4
    for (int t = tid; t < 2048; t += 256) {
        int row = t >> 6;
        int c   = (t & 63) * 4;
        float4 v = *(const float4*)(Z + (long)(m0 + row) * EMBED_DIM + c);
        Zs[row][c + 0] = v.x; Zs[row][c + 1] = v.y;
        Zs[row][c + 2] = v.z; Zs[row][c + 3] = v.w;
    }
    __syncthreads();

    const int lr = tid >> 2;         // 0..63 code row within chunk
    const int lc = (tid & 3) * 4;    // float4 col

    float best[2]  = {3.4e38f, 3.4e38f};
    int   bidx[2]  = {0, 0};

    for (int nc = 0; nc < EMBED_NUM; nc += 64) {
        float acc[2][4];
        #pragma unroll
        for (int i = 0; i < 2; i++)
            #pragma unroll
            for (int j = 0; j < 4; j++) acc[i][j] = 0.f;

        for (int k0 = 0; k0 < EMBED_DIM; k0 += GBK) {
            float4 bv = *(const float4*)(E + (long)(nc + lr) * EMBED_DIM + k0 + lc);
            Es[lc + 0][lr] = bv.x; Es[lc + 1][lr] = bv.y;
            Es[lc + 2][lr] = bv.z; Es[lc + 3][lr] = bv.w;
            __syncthreads();

            #pragma unroll
            for (int kk = 0; kk < GBK; kk++) {
                float a0 = Zs[ty * 2 + 0][k0 + kk];
                float a1 = Zs[ty * 2 + 1][k0 + kk];
                float4 b = *(const float4*)&Es[kk][tx * 4];
                float rb[4] = {b.x, b.y, b.z, b.w};
                #pragma unroll
                for (int j = 0; j < 4; j++) {
                    acc[0][j] = fmaf(a0, rb[j], acc[0][j]);
                    acc[1][j] = fmaf(a1, rb[j], acc[1][j]);
                }
            }
            __syncthreads();
        }

        #pragma unroll
        for (int j = 0; j < 4; j++) {
            int n = nc + tx * 4 + j;
            float en = enorm[n];
            #pragma unroll
            for (int i = 0; i < 2; i++) {
                float s = fmaf(-2.f, acc[i][j], en);
                if (s < best[i]) { best[i] = s; bidx[i] = n; }
            }
        }
    }

    #pragma unroll
    for (int i = 0; i < 2; i++) {
        rs[ty * 2 + i][tx] = best[i];
        ri[ty * 2 + i][tx] = bidx[i];
    }
    __syncthreads();

    if (tid < 32) {
        float b  = 3.4e38f;
        int   bi = 0x7FFFFFFF;
        #pragma unroll
        for (int t = 0; t < 16; t++) {
            float s = rs[tid][t];
            int   ii = ri[tid][t];
            if (s < b || (s == b && ii < bi)) { b = s; bi = ii; }
        }
        idxOut[m0 + tid] = bi;
    }
}

// ---------------------------------------------------------------------------
// launch
// ---------------------------------------------------------------------------
extern "C" void kernel_launch(void* const* d_in, const int* in_sizes, int n_in,
                              void* d_out, int out_size) {
    const float* x   = (const float*)d_in[0];
    const float* W1  = (const float*)d_in[1];
    const float* b1  = (const float*)d_in[2];
    const float* W2  = (const float*)d_in[3];
    const float* b2  = (const float*)d_in[4];
    const float* W3  = (const float*)d_in[5];
    const float* b3  = (const float*)d_in[6];
    const float* W4  = (const float*)d_in[7];
    const float* b4  = (const float*)d_in[8];
    const float* emb = (const float*)d_in[9];
    float* out = (float*)d_out;

    float *h1, *ze, *h3, *en;
    int* idx;
    cudaGetSymbolAddress((void**)&h1, g_h1);
    cudaGetSymbolAddress((void**)&ze, g_ze);
    cudaGetSymbolAddress((void**)&h3, g_h3);
    cudaGetSymbolAddress((void**)&en, g_enorm);
    cudaGetSymbolAddress((void**)&idx, g_idx);

    // ||e_j||^2
    enorm_kernel<<<EMBED_NUM / 8, 256>>>(emb, en);

    // G1: h1 = relu(x @ W1^T + b1)    (16384,400,1024)
    gemm_bias_act<1, false><<<dim3((HIDDEN + 63) / 64, BZ / 64), 256>>>(
        x, W1, b1, h1, BZ, HIDDEN, INPUT_DIM, nullptr);

    // G2: z_e = h1 @ W2^T + b2        (16384,256,400)
    gemm_bias_act<0, false><<<dim3(EMBED_DIM / 64, BZ / 64), 256>>>(
        h1, W2, b2, ze, BZ, EMBED_DIM, HIDDEN, nullptr);

    // VQ: idx = argmin_j ||z_e - e_j||^2
    vq_argmin<<<BZ / 32, 256>>>(ze, emb, en, idx);

    // G3: h3 = relu(emb[idx] @ W3^T + b3)   (16384,400,256) gather fused
    gemm_bias_act<1, true><<<dim3((HIDDEN + 63) / 64, BZ / 64), 256>>>(
        emb, W3, b3, h3, BZ, HIDDEN, EMBED_DIM, idx);

    // G4: out = sigmoid(h3 @ W4^T + b4)     (16384,1024,400)
    gemm_bias_act<2, false><<<dim3(INPUT_DIM / 64, BZ / 64), 256>>>(
        h3, W4, b4, out, BZ, INPUT_DIM, HIDDEN, nullptr);
}

// round 5
// speedup vs baseline: 1.3501x; 1.3478x over previous
#include <cuda_runtime.h>
#include <cuda_bf16.h>
#include <cstdint>

typedef __nv_bfloat16 bf16;

#define BZ        16384
#define INPUT_DIM 1024
#define HIDDEN    400
#define EMBED_DIM 256
#define EMBED_NUM 2048

// ===========================================================================
// Scratch (__device__ globals; allocation-free)
// A-ext: [m][2*KP]  blocks [a0|a1]
// B-ext: [n][3*KP]  blocks [b0|b0|b1]   (product pairing a0b0+a1b0+a0b1)
// ===========================================================================
__device__ __align__(16) bf16 g_xext [16384L * 2048];  // KP=1024
__device__ __align__(16) bf16 g_h1e  [16384L * 832];   // KP=416
__device__ __align__(16) bf16 g_zee  [16384L * 512];   // KP=256
__device__ __align__(16) bf16 g_h3e  [16384L * 832];   // KP=416
__device__ __align__(16) bf16 g_w1e  [448L   * 3072];  // N=400->448, KP=1024
__device__ __align__(16) bf16 g_w2e  [256L   * 1248];  // KP=416
__device__ __align__(16) bf16 g_w3e  [448L   * 768];   // KP=256
__device__ __align__(16) bf16 g_w4e  [1024L  * 1248];  // KP=416
__device__ __align__(16) bf16 g_embvq[2048L  * 768];   // KP=256
__device__ __align__(16) bf16 g_embdec[2048L * 512];   // A-ext of emb, KP=256
__device__ float g_en[EMBED_NUM];
__device__ int   g_idx[BZ];
__device__ float g_pv[BZ * 32L];
__device__ int   g_pi[BZ * 32L];

// ===========================================================================
// PTX helpers
// ===========================================================================
__device__ __forceinline__ uint32_t smem_u32(const void* p) {
    uint32_t a;
    asm("{ .reg .u64 t; cvta.to.shared.u64 t, %1; cvt.u32.u64 %0, t; }"
        : "=r"(a) : "l"(p));
    return a;
}

#define CP_ASYNC16(dst, src) \
    asm volatile("cp.async.cg.shared.global [%0], [%1], 16;" :: "r"(dst), "l"(src) : "memory")
#define CP_COMMIT() asm volatile("cp.async.commit_group;" ::: "memory")
#define CP_WAIT1()  asm volatile("cp.async.wait_group 1;" ::: "memory")
#define CP_WAIT0()  asm volatile("cp.async.wait_group 0;" ::: "memory")

#define LDMX4(r0, r1, r2, r3, addr) \
    asm volatile("ldmatrix.sync.aligned.m8n8.x4.shared.b16 {%0,%1,%2,%3}, [%4];" \
        : "=r"(r0), "=r"(r1), "=r"(r2), "=r"(r3) : "r"(addr))

#define MMA16816(d, a, b0v, b1v) \
    asm volatile("mma.sync.aligned.m16n8k16.row.col.f32.bf16.bf16.f32 " \
        "{%0,%1,%2,%3}, {%4,%5,%6,%7}, {%8,%9}, {%0,%1,%2,%3};" \
        : "+f"((d)[0]), "+f"((d)[1]), "+f"((d)[2]), "+f"((d)[3]) \
        : "r"((a)[0]), "r"((a)[1]), "r"((a)[2]), "r"((a)[3]), "r"(b0v), "r"(b1v))

// ===========================================================================
// Prep kernels
// ===========================================================================
__global__ void enorm_kernel(const float* __restrict__ E, float* __restrict__ en) {
    int j    = blockIdx.x * 8 + (threadIdx.x >> 5);
    int lane = threadIdx.x & 31;
    const float* row = E + (long)j * EMBED_DIM;
    float s = 0.f;
    for (int k = lane; k < EMBED_DIM; k += 32) { float v = row[k]; s += v * v; }
    #pragma unroll
    for (int o = 16; o; o >>= 1) s += __shfl_xor_sync(0xFFFFFFFFu, s, o);
    if (lane == 0) en[j] = s;
}

// A-side 2-term split (K == KP for its uses)
__global__ void conv_A(const float* __restrict__ in, bf16* __restrict__ out,
                       long rows, int K) {
    long tot = rows * K;
    for (long i = blockIdx.x * 256L + threadIdx.x; i < tot; i += gridDim.x * 256L) {
        long m = i / K;
        int  k = (int)(i - m * K);
        float v = in[i];
        bf16 t0 = __float2bfloat16(v);
        float r = v - __bfloat162float(t0);
        bf16 t1 = __float2bfloat16(r);
        bf16* o = out + m * (2L * K) + k;
        o[0] = t0; o[K] = t1;
    }
}

// B-side: blocks [b0|b0|b1]; zero-pads n>=N, k>=K
__global__ void conv_B(const float* __restrict__ W, bf16* __restrict__ out,
                       int N, int Npad, int K, int KP) {
    long tot = (long)Npad * KP;
    for (long i = blockIdx.x * 256L + threadIdx.x; i < tot; i += gridDim.x * 256L) {
        int n = (int)(i / KP);
        int k = (int)(i - (long)n * KP);
        float v = (n < N && k < K) ? W[(long)n * K + k] : 0.f;
        bf16 s0 = __float2bfloat16(v);
        float r = v - __bfloat162float(s0);
        bf16 s1 = __float2bfloat16(r);
        bf16* o = out + (long)n * (3L * KP) + k;
        o[0] = s0; o[KP] = s0; o[2L * KP] = s1;
    }
}

// zero K-padding of activation ext buffers (k in [K,KP), both split blocks)
__global__ void zero_pad(bf16* __restrict__ buf, long rows, int K, int KP) {
    int pad = KP - K;
    long tot = rows * 2L * pad;
    bf16 z = __float2bfloat16(0.f);
    for (long i = blockIdx.x * 256L + threadIdx.x; i < tot; i += gridDim.x * 256L) {
        long m = i / (2 * pad);
        int rem = (int)(i - m * (2 * pad));
        int s = rem / pad, k = K + (rem - (rem / pad) * pad);
        buf[m * (2L * KP) + (long)s * KP + k] = z;
    }
}

__global__ void reduce_argmin(const float* __restrict__ pv, const int* __restrict__ pi,
                              int* __restrict__ idx) {
    int m = blockIdx.x * 256 + threadIdx.x;
    float b = 3.4e38f; int bi = 0;
    #pragma unroll
    for (int t = 0; t < 32; t++) {
        float v = pv[(long)m * 32 + t];
        if (v < b) { b = v; bi = pi[(long)m * 32 + t]; }
    }
    idx[m] = bi;
}

// ===========================================================================
// HMMA GEMM: C[M, Npad] = act(Aext @ Bext^T + bias), BM=128 BN=64 BK=32.
// STAGE: 0 = relu + 2-term-split store, 1 = split store (no act),
//        2 = VQ argmin partials, 4 = sigmoid fp32 store.
// ===========================================================================
template <int STAGE, bool GATHER>
__global__ __launch_bounds__(256, 2)
void hgemm(const bf16* __restrict__ A, int Arow, int KP, int KPC, int NC,
           const bf16* __restrict__ B, int Brow,
           const float* __restrict__ bias, int Nreal,
           const int* __restrict__ gidx,
           bf16* __restrict__ outE, int outRow, int outKP,
           float* __restrict__ outF,
           float* __restrict__ pv, int* __restrict__ pi) {
    extern __shared__ __align__(16) char smem[];
    const uint32_t smBase = smem_u32(smem);
    // layout: A bufs [0, 2*10240), B bufs [20480, 20480 + 2*5120)
    const int tid  = threadIdx.x;
    const int lane = tid & 31, wid = tid >> 5;
    const int warpM = wid >> 1, warpN = wid & 1;
    const int m0 = blockIdx.x * 128;
    const int n0 = blockIdx.y * 64;

    // ---- load assignments ----
    const int ar0 = tid >> 2, ar1 = 64 + (tid >> 2);
    const int col2 = tid & 3;
    long gr0 = GATHER ? (long)gidx[m0 + ar0] : (long)(m0 + ar0);
    long gr1 = GATHER ? (long)gidx[m0 + ar1] : (long)(m0 + ar1);
    const bf16* aB0 = A + gr0 * Arow;
    const bf16* aB1 = A + gr1 * Arow;
    const bf16* bB  = B + (long)(n0 + (tid >> 2)) * Brow + col2 * 8;
    const uint32_t aD0 = smBase + ar0 * 80 + col2 * 16;
    const uint32_t aD1 = smBase + ar1 * 80 + col2 * 16;
    const uint32_t bD  = smBase + 20480 + (tid >> 2) * 80 + col2 * 16;

    float acc[2][4][4];
    #pragma unroll
    for (int t = 0; t < 2; t++)
        #pragma unroll
        for (int nt = 0; nt < 4; nt++)
            #pragma unroll
            for (int r = 0; r < 4; r++) acc[t][nt][r] = 0.f;

    // ---- prologue: issue chunk 0 ----
    {
        int akoff = col2 * 8;  // c=0 -> p=0, kin=0
        CP_ASYNC16(aD0, aB0 + akoff);
        CP_ASYNC16(aD1, aB1 + akoff);
        CP_ASYNC16(bD,  bB);
        CP_COMMIT();
    }

    const int gRow  = lane >> 2;
    const int cPair = (lane & 3) * 2;

    for (int c = 0; c < NC; c++) {
        if (c + 1 < NC) {
            const int cn  = c + 1;
            const int buf = cn & 1;
            const int p   = cn / KPC;
            const int akoff = ((p == 1) ? KP : 0) + (cn - p * KPC) * 32 + col2 * 8;
            CP_ASYNC16(aD0 + buf * 10240, aB0 + akoff);
            CP_ASYNC16(aD1 + buf * 10240, aB1 + akoff);
            CP_ASYNC16(bD  + buf * 5120,  bB + (long)cn * 32);
            CP_COMMIT();
            CP_WAIT1();
        } else {
            CP_WAIT0();
        }
        __syncthreads();

        const int buf = c & 1;
        const uint32_t aW = smBase + buf * 10240 + (warpM * 32) * 80;
        const uint32_t bW = smBase + 20480 + buf * 5120 + (warpN * 32) * 80;

        #pragma unroll
        for (int kh = 0; kh < 2; kh++) {
            uint32_t a[2][4], bf_[2][4];
            const uint32_t lrow = (lane & 15) * 80;
            const uint32_t lcol = (kh * 2 + (lane >> 4)) * 16;
            #pragma unroll
            for (int t = 0; t < 2; t++)
                LDMX4(a[t][0], a[t][1], a[t][2], a[t][3], aW + (t * 16) * 80 + lrow + lcol);
            #pragma unroll
            for (int g = 0; g < 2; g++)
                LDMX4(bf_[g][0], bf_[g][1], bf_[g][2], bf_[g][3], bW + (g * 16) * 80 + lrow + lcol);
            #pragma unroll
            for (int t = 0; t < 2; t++)
                #pragma unroll
                for (int nt = 0; nt < 4; nt++)
                    MMA16816(acc[t][nt], a[t], bf_[nt >> 1][nt & 1], bf_[nt >> 1][(nt & 1) + 2]);
        }
        __syncthreads();
    }

    // ---- epilogue ----
    if (STAGE == 2) {
        float* sv = (float*)smem;
        int*   si = (int*)(smem + 1024);
        #pragma unroll
        for (int t = 0; t < 2; t++) {
            #pragma unroll
            for (int h = 0; h < 2; h++) {
                float bv = 3.4e38f; int bi = 0x7FFFFFFF;
                #pragma unroll
                for (int nt = 0; nt < 4; nt++) {
                    #pragma unroll
                    for (int cc = 0; cc < 2; cc++) {
                        int n = n0 + warpN * 32 + nt * 8 + cPair + cc;
                        float d = fmaf(-2.f, acc[t][nt][h * 2 + cc], bias[n]);
                        if (d < bv) { bv = d; bi = n; }
                    }
                }
                #pragma unroll
                for (int o = 1; o <= 2; o <<= 1) {
                    float ov = __shfl_xor_sync(0xFFFFFFFFu, bv, o);
                    int   oi = __shfl_xor_sync(0xFFFFFFFFu, bi, o);
                    if (ov < bv || (ov == bv && oi < bi)) { bv = ov; bi = oi; }
                }
                if ((lane & 3) == 0) {
                    int r = warpM * 32 + t * 16 + h * 8 + gRow;
                    sv[r * 2 + warpN] = bv;
                    si[r * 2 + warpN] = bi;
                }
            }
        }
        __syncthreads();
        if (tid < 128) {
            float v0 = sv[tid * 2], v1 = sv[tid * 2 + 1];
            int   i0 = si[tid * 2], i1 = si[tid * 2 + 1];
            float bv; int bi;
            if (v1 < v0 || (v1 == v0 && i1 < i0)) { bv = v1; bi = i1; }
            else                                  { bv = v0; bi = i0; }
            pv[(long)(m0 + tid) * 32 + blockIdx.y] = bv;
            pi[(long)(m0 + tid) * 32 + blockIdx.y] = bi;
        }
    } else {
        #pragma unroll
        for (int t = 0; t < 2; t++) {
            #pragma unroll
            for (int nt = 0; nt < 4; nt++) {
                const int n = n0 + warpN * 32 + nt * 8 + cPair;
                if (n >= Nreal) continue;
                const float b0 = bias[n], b1 = bias[n + 1];
                #pragma unroll
                for (int h = 0; h < 2; h++) {
                    const long m = m0 + warpM * 32 + t * 16 + h * 8 + gRow;
                    float v0 = acc[t][nt][h * 2 + 0] + b0;
                    float v1 = acc[t][nt][h * 2 + 1] + b1;
                    if (STAGE == 0) { v0 = fmaxf(v0, 0.f); v1 = fmaxf(v1, 0.f); }
                    if (STAGE == 4) {
                        float s0 = 1.f / (1.f + __expf(-v0));
                        float s1 = 1.f / (1.f + __expf(-v1));
                        *(float2*)(outF + m * INPUT_DIM + n) = make_float2(s0, s1);
                    } else {
                        bf16 t00 = __float2bfloat16(v0);
                        bf16 t01 = __float2bfloat16(v1);
                        float r0 = v0 - __bfloat162float(t00);
                        float r1 = v1 - __bfloat162float(t01);
                        bf16 t10 = __float2bfloat16(r0);
                        bf16 t11 = __float2bfloat16(r1);
                        bf16* d = outE + m * outRow + n;
                        *(__nv_bfloat162*)(d)         = __nv_bfloat162(t00, t01);
                        *(__nv_bfloat162*)(d + outKP) = __nv_bfloat162(t10, t11);
                    }
                }
            }
        }
    }
}

// ===========================================================================
// Launch
// ===========================================================================
extern "C" void kernel_launch(void* const* d_in, const int* in_sizes, int n_in,
                              void* d_out, int out_size) {
    const float* x   = (const float*)d_in[0];
    const float* W1  = (const float*)d_in[1];
    const float* b1  = (const float*)d_in[2];
    const float* W2  = (const float*)d_in[3];
    const float* b2  = (const float*)d_in[4];
    const float* W3  = (const float*)d_in[5];
    const float* b3  = (const float*)d_in[6];
    const float* W4  = (const float*)d_in[7];
    const float* b4  = (const float*)d_in[8];
    const float* emb = (const float*)d_in[9];
    float* out = (float*)d_out;

    bf16 *xext, *h1e, *zee, *h3e, *w1e, *w2e, *w3e, *w4e, *embvq, *embdec;
    float *en, *pv; int *pi, *idx;
    cudaGetSymbolAddress((void**)&xext,   g_xext);
    cudaGetSymbolAddress((void**)&h1e,    g_h1e);
    cudaGetSymbolAddress((void**)&zee,    g_zee);
    cudaGetSymbolAddress((void**)&h3e,    g_h3e);
    cudaGetSymbolAddress((void**)&w1e,    g_w1e);
    cudaGetSymbolAddress((void**)&w2e,    g_w2e);
    cudaGetSymbolAddress((void**)&w3e,    g_w3e);
    cudaGetSymbolAddress((void**)&w4e,    g_w4e);
    cudaGetSymbolAddress((void**)&embvq,  g_embvq);
    cudaGetSymbolAddress((void**)&embdec, g_embdec);
    cudaGetSymbolAddress((void**)&en,     g_en);
    cudaGetSymbolAddress((void**)&pv,     g_pv);
    cudaGetSymbolAddress((void**)&pi,     g_pi);
    cudaGetSymbolAddress((void**)&idx,    g_idx);

    const int SMEM = 30720;

    // ---- prep ----
    enorm_kernel<<<EMBED_NUM / 8, 256>>>(emb, en);
    conv_A<<<4096, 256>>>(x,   xext,   (long)BZ, INPUT_DIM);
    conv_A<<<512,  256>>>(emb, embdec, (long)EMBED_NUM, EMBED_DIM);
    conv_B<<<2048, 256>>>(W1,  w1e,   HIDDEN,    448,  INPUT_DIM, 1024);
    conv_B<<<512,  256>>>(W2,  w2e,   EMBED_DIM, 256,  HIDDEN,    416);
    conv_B<<<512,  256>>>(emb, embvq, EMBED_NUM, 2048, EMBED_DIM, 256);
    conv_B<<<512,  256>>>(W3,  w3e,   HIDDEN,    448,  EMBED_DIM, 256);
    conv_B<<<1024, 256>>>(W4,  w4e,   INPUT_DIM, 1024, HIDDEN,    416);
    zero_pad<<<512, 256>>>(h1e, BZ, HIDDEN, 416);
    zero_pad<<<512, 256>>>(h3e, BZ, HIDDEN, 416);

    // ---- G1: h1 = relu(x @ W1^T + b1) ----
    hgemm<0, false><<<dim3(128, 7), 256, SMEM>>>(
        xext, 2048, 1024, 32, 96, w1e, 3072, b1, HIDDEN, nullptr,
        h1e, 832, 416, nullptr, nullptr, nullptr);

    // ---- G2: z_e = h1 @ W2^T + b2 ----
    hgemm<1, false><<<dim3(128, 4), 256, SMEM>>>(
        h1e, 832, 416, 13, 39, w2e, 1248, b2, EMBED_DIM, nullptr,
        zee, 512, 256, nullptr, nullptr, nullptr);

    // ---- VQ: partial argmin over 32 N-tiles ----
    hgemm<2, false><<<dim3(128, 32), 256, SMEM>>>(
        zee, 512, 256, 8, 24, embvq, 768, en, EMBED_NUM, nullptr,
        nullptr, 0, 0, nullptr, pv, pi);
    reduce_argmin<<<BZ / 256, 256>>>(pv, pi, idx);

    // ---- G3: h3 = relu(emb[idx] @ W3^T + b3), gather fused ----
    hgemm<0, true><<<dim3(128, 7), 256, SMEM>>>(
        embdec, 512, 256, 8, 24, w3e, 768, b3, HIDDEN, idx,
        h3e, 832, 416, nullptr, nullptr, nullptr);

    // ---- G4: out = sigmoid(h3 @ W4^T + b4) ----
    hgemm<4, false><<<dim3(128, 16), 256, SMEM>>>(
        h3e, 832, 416, 13, 39, w4e, 1248, b4, INPUT_DIM, nullptr,
        nullptr, 0, 0, out, nullptr, nullptr);
}

// round 6
// speedup vs baseline: 1.7556x; 1.3004x over previous
#include <cuda_runtime.h>
#include <cuda_bf16.h>
#include <cstdint>

typedef __nv_bfloat16 bf16;

#define BZ        16384
#define INPUT_DIM 1024
#define HIDDEN    400
#define EMBED_DIM 256
#define EMBED_NUM 2048

// ===========================================================================
// Scratch (__device__ globals; allocation-free)
// A-ext: [m][2*KP]  blocks [a0|a1]
// B-ext: [n][3*KP]  blocks [b0|b0|b1]  (products a0b0 + a1b0 + a0b1)
// ===========================================================================
__device__ __align__(16) bf16 g_xext [16384L * 2048];  // KP=1024
__device__ __align__(16) bf16 g_h1e  [16384L * 832];   // KP=416
__device__ __align__(16) bf16 g_zee  [16384L * 512];   // KP=256
__device__ __align__(16) bf16 g_h3e  [16384L * 832];   // KP=416
__device__ __align__(16) bf16 g_w1e  [512L   * 3072];  // N 400->512, KP=1024
__device__ __align__(16) bf16 g_w2e  [256L   * 1248];  // KP=416
__device__ __align__(16) bf16 g_w3e  [512L   * 768];   // N 400->512, KP=256
__device__ __align__(16) bf16 g_w4e  [1024L  * 1248];  // KP=416
__device__ __align__(16) bf16 g_embvq[2048L  * 768];   // KP=256
__device__ __align__(16) bf16 g_embdec[2048L * 512];   // A-ext of emb, KP=256
__device__ float g_en[EMBED_NUM];
__device__ int   g_idx[BZ];
__device__ float g_pv[BZ * 16L];
__device__ int   g_pi[BZ * 16L];

// ===========================================================================
// PTX helpers
// ===========================================================================
__device__ __forceinline__ uint32_t smem_u32(const void* p) {
    uint32_t a;
    asm("{ .reg .u64 t; cvta.to.shared.u64 t, %1; cvt.u32.u64 %0, t; }"
        : "=r"(a) : "l"(p));
    return a;
}

#define CP_ASYNC16(dst, src) \
    asm volatile("cp.async.cg.shared.global [%0], [%1], 16;" :: "r"(dst), "l"(src) : "memory")
#define CP_COMMIT() asm volatile("cp.async.commit_group;" ::: "memory")
#define CP_WAIT2()  asm volatile("cp.async.wait_group 2;" ::: "memory")
#define CP_WAIT1()  asm volatile("cp.async.wait_group 1;" ::: "memory")
#define CP_WAIT0()  asm volatile("cp.async.wait_group 0;" ::: "memory")

#define LDMX4(r0, r1, r2, r3, addr) \
    asm volatile("ldmatrix.sync.aligned.m8n8.x4.shared.b16 {%0,%1,%2,%3}, [%4];" \
        : "=r"(r0), "=r"(r1), "=r"(r2), "=r"(r3) : "r"(addr))

#define MMA16816(d, a, b0v, b1v) \
    asm volatile("mma.sync.aligned.m16n8k16.row.col.f32.bf16.bf16.f32 " \
        "{%0,%1,%2,%3}, {%4,%5,%6,%7}, {%8,%9}, {%0,%1,%2,%3};" \
        : "+f"((d)[0]), "+f"((d)[1]), "+f"((d)[2]), "+f"((d)[3]) \
        : "r"((a)[0]), "r"((a)[1]), "r"((a)[2]), "r"((a)[3]), "r"(b0v), "r"(b1v))

// ===========================================================================
// Prep kernels
// ===========================================================================
__global__ void enorm_kernel(const float* __restrict__ E, float* __restrict__ en) {
    int j    = blockIdx.x * 8 + (threadIdx.x >> 5);
    int lane = threadIdx.x & 31;
    const float* row = E + (long)j * EMBED_DIM;
    float s = 0.f;
    for (int k = lane; k < EMBED_DIM; k += 32) { float v = row[k]; s += v * v; }
    #pragma unroll
    for (int o = 16; o; o >>= 1) s += __shfl_xor_sync(0xFFFFFFFFu, s, o);
    if (lane == 0) en[j] = s;
}

// A-side 2-term split (K == KP for its uses)
__global__ void conv_A(const float* __restrict__ in, bf16* __restrict__ out,
                       long rows, int K) {
    long tot = rows * K;
    for (long i = blockIdx.x * 256L + threadIdx.x; i < tot; i += gridDim.x * 256L) {
        long m = i / K;
        int  k = (int)(i - m * K);
        float v = in[i];
        bf16 t0 = __float2bfloat16(v);
        float r = v - __bfloat162float(t0);
        bf16 t1 = __float2bfloat16(r);
        bf16* o = out + m * (2L * K) + k;
        o[0] = t0; o[K] = t1;
    }
}

// B-side: blocks [b0|b0|b1]; zero-pads n>=N, k>=K
__global__ void conv_B(const float* __restrict__ W, bf16* __restrict__ out,
                       int N, int Npad, int K, int KP) {
    long tot = (long)Npad * KP;
    for (long i = blockIdx.x * 256L + threadIdx.x; i < tot; i += gridDim.x * 256L) {
        int n = (int)(i / KP);
        int k = (int)(i - (long)n * KP);
        float v = (n < N && k < K) ? W[(long)n * K + k] : 0.f;
        bf16 s0 = __float2bfloat16(v);
        float r = v - __bfloat162float(s0);
        bf16 s1 = __float2bfloat16(r);
        bf16* o = out + (long)n * (3L * KP) + k;
        o[0] = s0; o[KP] = s0; o[2L * KP] = s1;
    }
}

// zero K-padding of activation ext buffers (k in [K,KP), both split blocks)
__global__ void zero_pad(bf16* __restrict__ buf, long rows, int K, int KP) {
    int pad = KP - K;
    long tot = rows * 2L * pad;
    bf16 z = __float2bfloat16(0.f);
    for (long i = blockIdx.x * 256L + threadIdx.x; i < tot; i += gridDim.x * 256L) {
        long m = i / (2 * pad);
        int rem = (int)(i - m * (2 * pad));
        int s = rem / pad, k = K + (rem - (rem / pad) * pad);
        buf[m * (2L * KP) + (long)s * KP + k] = z;
    }
}

__global__ void reduce_argmin(const float* __restrict__ pv, const int* __restrict__ pi,
                              int* __restrict__ idx) {
    int m = blockIdx.x * 256 + threadIdx.x;
    float b = 3.4e38f; int bi = 0;
    #pragma unroll
    for (int t = 0; t < 16; t++) {
        float v = pv[(long)m * 16 + t];
        if (v < b) { b = v; bi = pi[(long)m * 16 + t]; }
    }
    idx[m] = bi;
}

// ===========================================================================
// HMMA GEMM: BM=128, BN=128, BK=32, 4-stage cp.async pipeline, 256 thr.
// 8 warps = 2(M) x 4(N); warp tile 64x32; 32 MMA(m16n8k16)/warp/chunk.
// STAGE: 0 = relu + split store, 1 = split store, 2 = VQ argmin, 4 = sigmoid.
// ===========================================================================
#define NSTG   4
#define STGB   20480          // bytes per stage (A 10240 + B 10240)
#define B_OFF  (NSTG * 10240) // B region start: 40960

template <int STAGE, bool GATHER>
__global__ __launch_bounds__(256, 2)
void hgemm(const bf16* __restrict__ A, int Arow, int KP, int KPC, int NC,
           const bf16* __restrict__ B, int Brow,
           const float* __restrict__ bias, int Nreal,
           const int* __restrict__ gidx,
           bf16* __restrict__ outE, int outRow, int outKP,
           float* __restrict__ outF,
           float* __restrict__ pv, int* __restrict__ pi, int nParts) {
    extern __shared__ __align__(16) char smem[];
    const uint32_t smBase = smem_u32(smem);
    const int tid  = threadIdx.x;
    const int lane = tid & 31, wid = tid >> 5;
    const int warpM = wid >> 2, warpN = wid & 3;
    const int m0 = blockIdx.x * 128;
    const int n0 = blockIdx.y * 128;

    // ---- cp.async assignments: thread covers A rows r, r+64 and B rows r, r+64
    const int r4  = tid >> 2;     // 0..63
    const int c16 = tid & 3;      // 16B seg within 64B row-chunk
    long gr0 = GATHER ? (long)gidx[m0 + r4]      : (long)(m0 + r4);
    long gr1 = GATHER ? (long)gidx[m0 + 64 + r4] : (long)(m0 + 64 + r4);
    const bf16* aP0 = A + gr0 * (long)Arow;
    const bf16* aP1 = A + gr1 * (long)Arow;
    const bf16* bP0 = B + (long)(n0 + r4) * Brow + c16 * 8;
    const bf16* bP1 = B + (long)(n0 + 64 + r4) * Brow + c16 * 8;
    const uint32_t aD0 = smBase + r4 * 80 + c16 * 16;
    const uint32_t aD1 = aD0 + 64 * 80;
    const uint32_t bD0 = smBase + B_OFF + r4 * 80 + c16 * 16;
    const uint32_t bD1 = bD0 + 64 * 80;

    float acc[4][4][4];
    #pragma unroll
    for (int mt = 0; mt < 4; mt++)
        #pragma unroll
        for (int nt = 0; nt < 4; nt++)
            #pragma unroll
            for (int r = 0; r < 4; r++) acc[mt][nt][r] = 0.f;

    auto issue = [&](int cc) {
        const uint32_t st = (uint32_t)(cc & 3) * 10240u;
        const int p = cc / KPC;
        const int akoff = ((p == 1) ? KP : 0) + (cc - p * KPC) * 32 + c16 * 8;
        const long bk = (long)cc * 32;
        CP_ASYNC16(aD0 + st, aP0 + akoff);
        CP_ASYNC16(aD1 + st, aP1 + akoff);
        CP_ASYNC16(bD0 + st, bP0 + bk);
        CP_ASYNC16(bD1 + st, bP1 + bk);
        CP_COMMIT();
    };

    issue(0);
    if (NC > 1) issue(1);
    if (NC > 2) issue(2);

    const int gRow  = lane >> 2;
    const int cPair = (lane & 3) * 2;

    for (int c = 0; c < NC; c++) {
        if      (c + 2 < NC) CP_WAIT2();
        else if (c + 1 < NC) CP_WAIT1();
        else                 CP_WAIT0();
        __syncthreads();
        if (c + 3 < NC) issue(c + 3);

        const uint32_t st = (uint32_t)(c & 3) * 10240u;
        const uint32_t aW = smBase + st + (warpM * 64) * 80;
        const uint32_t bW = smBase + B_OFF + st + (warpN * 32) * 80;

        #pragma unroll
        for (int kh = 0; kh < 2; kh++) {
            uint32_t a[4][4], bf_[2][4];
            const uint32_t lrow = (lane & 15) * 80;
            const uint32_t lcol = kh * 32 + (lane >> 4) * 16;
            #pragma unroll
            for (int mt = 0; mt < 4; mt++)
                LDMX4(a[mt][0], a[mt][1], a[mt][2], a[mt][3],
                      aW + (mt * 16) * 80 + lrow + lcol);
            #pragma unroll
            for (int g = 0; g < 2; g++)
                LDMX4(bf_[g][0], bf_[g][1], bf_[g][2], bf_[g][3],
                      bW + (g * 16) * 80 + lrow + lcol);
            #pragma unroll
            for (int mt = 0; mt < 4; mt++)
                #pragma unroll
                for (int nt = 0; nt < 4; nt++)
                    MMA16816(acc[mt][nt], a[mt], bf_[nt >> 1][nt & 1], bf_[nt >> 1][(nt & 1) + 2]);
        }
    }
    __syncthreads();

    // ---- epilogue ----
    if (STAGE == 2) {
        float* sv = (float*)smem;
        int*   si = (int*)(smem + 2048);
        #pragma unroll
        for (int mt = 0; mt < 4; mt++) {
            #pragma unroll
            for (int h = 0; h < 2; h++) {
                float bv = 3.4e38f; int bi = 0x7FFFFFFF;
                #pragma unroll
                for (int nt = 0; nt < 4; nt++) {
                    #pragma unroll
                    for (int cc = 0; cc < 2; cc++) {
                        int n = n0 + warpN * 32 + nt * 8 + cPair + cc;
                        float d = fmaf(-2.f, acc[mt][nt][h * 2 + cc], bias[n]);
                        if (d < bv) { bv = d; bi = n; }
                    }
                }
                #pragma unroll
                for (int o = 1; o <= 2; o <<= 1) {
                    float ov = __shfl_xor_sync(0xFFFFFFFFu, bv, o);
                    int   oi = __shfl_xor_sync(0xFFFFFFFFu, bi, o);
                    if (ov < bv || (ov == bv && oi < bi)) { bv = ov; bi = oi; }
                }
                if ((lane & 3) == 0) {
                    int r = warpM * 64 + mt * 16 + h * 8 + gRow;
                    sv[r * 4 + warpN] = bv;
                    si[r * 4 + warpN] = bi;
                }
            }
        }
        __syncthreads();
        if (tid < 128) {
            float bv = 3.4e38f; int bi = 0x7FFFFFFF;
            #pragma unroll
            for (int t = 0; t < 4; t++) {
                float v = sv[tid * 4 + t];
                int   i2 = si[tid * 4 + t];
                if (v < bv || (v == bv && i2 < bi)) { bv = v; bi = i2; }
            }
            pv[(long)(m0 + tid) * nParts + blockIdx.y] = bv;
            pi[(long)(m0 + tid) * nParts + blockIdx.y] = bi;
        }
    } else {
        #pragma unroll
        for (int mt = 0; mt < 4; mt++) {
            #pragma unroll
            for (int nt = 0; nt < 4; nt++) {
                const int n = n0 + warpN * 32 + nt * 8 + cPair;
                if (n >= Nreal) continue;
                const float b0 = bias[n], b1 = bias[n + 1];
                #pragma unroll
                for (int h = 0; h < 2; h++) {
                    const long m = m0 + warpM * 64 + mt * 16 + h * 8 + gRow;
                    float v0 = acc[mt][nt][h * 2 + 0] + b0;
                    float v1 = acc[mt][nt][h * 2 + 1] + b1;
                    if (STAGE == 0) { v0 = fmaxf(v0, 0.f); v1 = fmaxf(v1, 0.f); }
                    if (STAGE == 4) {
                        float s0 = 1.f / (1.f + __expf(-v0));
                        float s1 = 1.f / (1.f + __expf(-v1));
                        *(float2*)(outF + m * INPUT_DIM + n) = make_float2(s0, s1);
                    } else {
                        bf16 t00 = __float2bfloat16(v0);
                        bf16 t01 = __float2bfloat16(v1);
                        float r0 = v0 - __bfloat162float(t00);
                        float r1 = v1 - __bfloat162float(t01);
                        bf16* d = outE + m * (long)outRow + n;
                        *(__nv_bfloat162*)(d)         = __nv_bfloat162(t00, t01);
                        *(__nv_bfloat162*)(d + outKP) =
                            __nv_bfloat162(__float2bfloat16(r0), __float2bfloat16(r1));
                    }
                }
            }
        }
    }
}

// ===========================================================================
// Launch
// ===========================================================================
extern "C" void kernel_launch(void* const* d_in, const int* in_sizes, int n_in,
                              void* d_out, int out_size) {
    const float* x   = (const float*)d_in[0];
    const float* W1  = (const float*)d_in[1];
    const float* b1  = (const float*)d_in[2];
    const float* W2  = (const float*)d_in[3];
    const float* b2  = (const float*)d_in[4];
    const float* W3  = (const float*)d_in[5];
    const float* b3  = (const float*)d_in[6];
    const float* W4  = (const float*)d_in[7];
    const float* b4  = (const float*)d_in[8];
    const float* emb = (const float*)d_in[9];
    float* out = (float*)d_out;

    bf16 *xext, *h1e, *zee, *h3e, *w1e, *w2e, *w3e, *w4e, *embvq, *embdec;
    float *en, *pv; int *pi, *idx;
    cudaGetSymbolAddress((void**)&xext,   g_xext);
    cudaGetSymbolAddress((void**)&h1e,    g_h1e);
    cudaGetSymbolAddress((void**)&zee,    g_zee);
    cudaGetSymbolAddress((void**)&h3e,    g_h3e);
    cudaGetSymbolAddress((void**)&w1e,    g_w1e);
    cudaGetSymbolAddress((void**)&w2e,    g_w2e);
    cudaGetSymbolAddress((void**)&w3e,    g_w3e);
    cudaGetSymbolAddress((void**)&w4e,    g_w4e);
    cudaGetSymbolAddress((void**)&embvq,  g_embvq);
    cudaGetSymbolAddress((void**)&embdec, g_embdec);
    cudaGetSymbolAddress((void**)&en,     g_en);
    cudaGetSymbolAddress((void**)&pv,     g_pv);
    cudaGetSymbolAddress((void**)&pi,     g_pi);
    cudaGetSymbolAddress((void**)&idx,    g_idx);

    const int SMEM = NSTG * STGB;  // 81920
    cudaFuncSetAttribute(hgemm<0, false>, cudaFuncAttributeMaxDynamicSharedMemorySize, SMEM);
    cudaFuncSetAttribute(hgemm<1, false>, cudaFuncAttributeMaxDynamicSharedMemorySize, SMEM);
    cudaFuncSetAttribute(hgemm<2, false>, cudaFuncAttributeMaxDynamicSharedMemorySize, SMEM);
    cudaFuncSetAttribute(hgemm<0, true >, cudaFuncAttributeMaxDynamicSharedMemorySize, SMEM);
    cudaFuncSetAttribute(hgemm<4, false>, cudaFuncAttributeMaxDynamicSharedMemorySize, SMEM);

    // ---- prep ----
    enorm_kernel<<<EMBED_NUM / 8, 256>>>(emb, en);
    conv_A<<<4096, 256>>>(x,   xext,   (long)BZ, INPUT_DIM);
    conv_A<<<512,  256>>>(emb, embdec, (long)EMBED_NUM, EMBED_DIM);
    conv_B<<<2048, 256>>>(W1,  w1e,   HIDDEN,    512,  INPUT_DIM, 1024);
    conv_B<<<512,  256>>>(W2,  w2e,   EMBED_DIM, 256,  HIDDEN,    416);
    conv_B<<<512,  256>>>(emb, embvq, EMBED_NUM, 2048, EMBED_DIM, 256);
    conv_B<<<512,  256>>>(W3,  w3e,   HIDDEN,    512,  EMBED_DIM, 256);
    conv_B<<<1024, 256>>>(W4,  w4e,   INPUT_DIM, 1024, HIDDEN,    416);
    zero_pad<<<512, 256>>>(h1e, BZ, HIDDEN, 416);
    zero_pad<<<512, 256>>>(h3e, BZ, HIDDEN, 416);

    // ---- G1: h1 = relu(x @ W1^T + b1) ----
    hgemm<0, false><<<dim3(128, 4), 256, SMEM>>>(
        xext, 2048, 1024, 32, 96, w1e, 3072, b1, HIDDEN, nullptr,
        h1e, 832, 416, nullptr, nullptr, nullptr, 0);

    // ---- G2: z_e = h1 @ W2^T + b2 ----
    hgemm<1, false><<<dim3(128, 2), 256, SMEM>>>(
        h1e, 832, 416, 13, 39, w2e, 1248, b2, EMBED_DIM, nullptr,
        zee, 512, 256, nullptr, nullptr, nullptr, 0);

    // ---- VQ: partial argmin over 16 N-tiles ----
    hgemm<2, false><<<dim3(128, 16), 256, SMEM>>>(
        zee, 512, 256, 8, 24, embvq, 768, en, EMBED_NUM, nullptr,
        nullptr, 0, 0, nullptr, pv, pi, 16);
    reduce_argmin<<<BZ / 256, 256>>>(pv, pi, idx);

    // ---- G3: h3 = relu(emb[idx] @ W3^T + b3), gather fused ----
    hgemm<0, true><<<dim3(128, 4), 256, SMEM>>>(
        embdec, 512, 256, 8, 24, w3e, 768, b3, HIDDEN, idx,
        h3e, 832, 416, nullptr, nullptr, nullptr, 0);

    // ---- G4: out = sigmoid(h3 @ W4^T + b4) ----
    hgemm<4, false><<<dim3(128, 8), 256, SMEM>>>(
        h3e, 832, 416, 13, 39, w4e, 1248, b4, INPUT_DIM, nullptr,
        nullptr, 0, 0, out, nullptr, nullptr, 0);
}

// round 7
// speedup vs baseline: 1.9192x; 1.0932x over previous
#include <cuda_runtime.h>
#include <cuda_bf16.h>
#include <cstdint>

typedef __nv_bfloat16 bf16;

#define BZ        16384
#define INPUT_DIM 1024
#define HIDDEN    400
#define EMBED_DIM 256
#define EMBED_NUM 2048

// ===========================================================================
// Scratch (__device__ globals; allocation-free)
// A-ext: [m][2*KP]  blocks [a0|a1]
// B-ext: [n][3*KP]  blocks [b0|b0|b1]  (products a0b0 + a1b0 + a0b1)
// ===========================================================================
__device__ __align__(16) bf16 g_xext [16384L * 2048];  // KP=1024
__device__ __align__(16) bf16 g_h1e  [16384L * 832];   // KP=416
__device__ __align__(16) bf16 g_zee  [16384L * 512];   // KP=256
__device__ __align__(16) bf16 g_h3e  [16384L * 832];   // KP=416
__device__ __align__(16) bf16 g_w1e  [512L   * 3072];  // N 400->512, KP=1024
__device__ __align__(16) bf16 g_w2e  [256L   * 1248];  // KP=416
__device__ __align__(16) bf16 g_w3e  [512L   * 768];   // N 400->512, KP=256
__device__ __align__(16) bf16 g_w4e  [1024L  * 1248];  // KP=416
__device__ __align__(16) bf16 g_embvq[2048L  * 768];   // KP=256
__device__ __align__(16) bf16 g_embdec[2048L * 512];   // A-ext of emb, KP=256
__device__ float g_en[EMBED_NUM];
__device__ int   g_idx[BZ];
__device__ float g_D[16384L * 2048];                   // approx VQ distances

// ===========================================================================
// PTX helpers
// ===========================================================================
__device__ __forceinline__ uint32_t smem_u32(const void* p) {
    uint32_t a;
    asm("{ .reg .u64 t; cvta.to.shared.u64 t, %1; cvt.u32.u64 %0, t; }"
        : "=r"(a) : "l"(p));
    return a;
}

#define CP_ASYNC16(dst, src) \
    asm volatile("cp.async.cg.shared.global [%0], [%1], 16;" :: "r"(dst), "l"(src) : "memory")
#define CP_COMMIT() asm volatile("cp.async.commit_group;" ::: "memory")
#define CP_WAIT2()  asm volatile("cp.async.wait_group 2;" ::: "memory")
#define CP_WAIT1()  asm volatile("cp.async.wait_group 1;" ::: "memory")
#define CP_WAIT0()  asm volatile("cp.async.wait_group 0;" ::: "memory")

#define LDMX4(r0, r1, r2, r3, addr) \
    asm volatile("ldmatrix.sync.aligned.m8n8.x4.shared.b16 {%0,%1,%2,%3}, [%4];" \
        : "=r"(r0), "=r"(r1), "=r"(r2), "=r"(r3) : "r"(addr))

#define MMA16816(d, a, b0v, b1v) \
    asm volatile("mma.sync.aligned.m16n8k16.row.col.f32.bf16.bf16.f32 " \
        "{%0,%1,%2,%3}, {%4,%5,%6,%7}, {%8,%9}, {%0,%1,%2,%3};" \
        : "+f"((d)[0]), "+f"((d)[1]), "+f"((d)[2]), "+f"((d)[3]) \
        : "r"((a)[0]), "r"((a)[1]), "r"((a)[2]), "r"((a)[3]), "r"(b0v), "r"(b1v))

// ===========================================================================
// Prep kernels
// ===========================================================================
__global__ void enorm_kernel(const float* __restrict__ E, float* __restrict__ en) {
    int j    = blockIdx.x * 8 + (threadIdx.x >> 5);
    int lane = threadIdx.x & 31;
    const float* row = E + (long)j * EMBED_DIM;
    float s = 0.f;
    for (int k = lane; k < EMBED_DIM; k += 32) { float v = row[k]; s += v * v; }
    #pragma unroll
    for (int o = 16; o; o >>= 1) s += __shfl_xor_sync(0xFFFFFFFFu, s, o);
    if (lane == 0) en[j] = s;
}

// A-side 2-term split (K == KP for its uses)
__global__ void conv_A(const float* __restrict__ in, bf16* __restrict__ out,
                       long rows, int K) {
    long tot = rows * K;
    for (long i = blockIdx.x * 256L + threadIdx.x; i < tot; i += gridDim.x * 256L) {
        long m = i / K;
        int  k = (int)(i - m * K);
        float v = in[i];
        bf16 t0 = __float2bfloat16(v);
        float r = v - __bfloat162float(t0);
        bf16 t1 = __float2bfloat16(r);
        bf16* o = out + m * (2L * K) + k;
        o[0] = t0; o[K] = t1;
    }
}

// B-side: blocks [b0|b0|b1]; zero-pads n>=N, k>=K
__global__ void conv_B(const float* __restrict__ W, bf16* __restrict__ out,
                       int N, int Npad, int K, int KP) {
    long tot = (long)Npad * KP;
    for (long i = blockIdx.x * 256L + threadIdx.x; i < tot; i += gridDim.x * 256L) {
        int n = (int)(i / KP);
        int k = (int)(i - (long)n * KP);
        float v = (n < N && k < K) ? W[(long)n * K + k] : 0.f;
        bf16 s0 = __float2bfloat16(v);
        float r = v - __bfloat162float(s0);
        bf16 s1 = __float2bfloat16(r);
        bf16* o = out + (long)n * (3L * KP) + k;
        o[0] = s0; o[KP] = s0; o[2L * KP] = s1;
    }
}

// zero K-padding of activation ext buffers (k in [K,KP), both split blocks)
__global__ void zero_pad(bf16* __restrict__ buf, long rows, int K, int KP) {
    int pad = KP - K;
    long tot = rows * 2L * pad;
    bf16 z = __float2bfloat16(0.f);
    for (long i = blockIdx.x * 256L + threadIdx.x; i < tot; i += gridDim.x * 256L) {
        long m = i / (2 * pad);
        int rem = (int)(i - m * (2 * pad));
        int s = rem / pad, k = K + (rem - (rem / pad) * pad);
        buf[m * (2L * KP) + (long)s * KP + k] = z;
    }
}

// ===========================================================================
// VQ scan + exact refine.
// Per row: min over approx D, collect candidates within DELTA, compute exact
// ||z - e||^2 (z = z0+z1 from split buffer, e = original fp32) and argmin.
// ===========================================================================
#define VQ_DELTA 0.5f

__global__ __launch_bounds__(256)
void scan_refine(const float* __restrict__ D, const bf16* __restrict__ zee,
                 const float* __restrict__ emb, int* __restrict__ idx) {
    const int wid = threadIdx.x >> 5, lane = threadIdx.x & 31;
    const long row = blockIdx.x * 8 + wid;
    const float* d = D + row * EMBED_NUM;

    float mn = 3.4e38f;
    for (int k = lane; k < EMBED_NUM; k += 32) mn = fminf(mn, d[k]);
    #pragma unroll
    for (int o = 16; o; o >>= 1) mn = fminf(mn, __shfl_xor_sync(0xFFFFFFFFu, mn, o));
    const float thr = mn + VQ_DELTA;

    __shared__ int cnt[8];
    __shared__ int cand[8][16];
    if (lane == 0) cnt[wid] = 0;
    __syncwarp();
    for (int k = lane; k < EMBED_NUM; k += 32) {
        if (d[k] <= thr) {
            int p = atomicAdd(&cnt[wid], 1);
            if (p < 16) cand[wid][p] = k;
        }
    }
    __syncwarp();
    const int nc = min(cnt[wid], 16);

    float z[8];
    #pragma unroll
    for (int t = 0; t < 8; t++) {
        int k = lane + t * 32;
        z[t] = __bfloat162float(zee[row * 512 + k])
             + __bfloat162float(zee[row * 512 + 256 + k]);
    }

    float bd = 3.4e38f; int bi = 0x7FFFFFFF;
    for (int c = 0; c < nc; c++) {
        const int j = cand[wid][c];
        const float* e = emb + (long)j * EMBED_DIM;
        float s = 0.f;
        #pragma unroll
        for (int t = 0; t < 8; t++) {
            float df = z[t] - e[lane + t * 32];
            s = fmaf(df, df, s);
        }
        #pragma unroll
        for (int o = 16; o; o >>= 1) s += __shfl_xor_sync(0xFFFFFFFFu, s, o);
        if (s < bd || (s == bd && j < bi)) { bd = s; bi = j; }
    }
    if (lane == 0) idx[row] = bi;
}

// ===========================================================================
// HMMA GEMM: BM=128, BN=128, BK=32, 4-stage cp.async pipeline, 256 thr.
// 8 warps = 2(M) x 4(N); warp tile 64x32; 32 MMA(m16n8k16)/warp/chunk.
// STAGE: 0 = relu + split store, 1 = split store, 4 = sigmoid fp32,
//        5 = VQ approx distance store (bias = ||e||^2, D = bias - 2*acc).
// ===========================================================================
#define NSTG   4
#define STGB   20480          // bytes per stage (A 10240 + B 10240)
#define B_OFF  (NSTG * 10240) // B region start: 40960

template <int STAGE, bool GATHER>
__global__ __launch_bounds__(256, 2)
void hgemm(const bf16* __restrict__ A, int Arow, int KP, int KPC, int NC,
           const bf16* __restrict__ B, int Brow,
           const float* __restrict__ bias, int Nreal,
           const int* __restrict__ gidx,
           bf16* __restrict__ outE, int outRow, int outKP,
           float* __restrict__ outF, int outFs) {
    extern __shared__ __align__(16) char smem[];
    const uint32_t smBase = smem_u32(smem);
    const int tid  = threadIdx.x;
    const int lane = tid & 31, wid = tid >> 5;
    const int warpM = wid >> 2, warpN = wid & 3;
    const int m0 = blockIdx.x * 128;
    const int n0 = blockIdx.y * 128;

    // ---- cp.async assignments: thread covers A rows r, r+64 and B rows r, r+64
    const int r4  = tid >> 2;     // 0..63
    const int c16 = tid & 3;      // 16B seg within 64B row-chunk
    long gr0 = GATHER ? (long)gidx[m0 + r4]      : (long)(m0 + r4);
    long gr1 = GATHER ? (long)gidx[m0 + 64 + r4] : (long)(m0 + 64 + r4);
    const bf16* aP0 = A + gr0 * (long)Arow;
    const bf16* aP1 = A + gr1 * (long)Arow;
    const bf16* bP0 = B + (long)(n0 + r4) * Brow + c16 * 8;
    const bf16* bP1 = B + (long)(n0 + 64 + r4) * Brow + c16 * 8;
    const uint32_t aD0 = smBase + r4 * 80 + c16 * 16;
    const uint32_t aD1 = aD0 + 64 * 80;
    const uint32_t bD0 = smBase + B_OFF + r4 * 80 + c16 * 16;
    const uint32_t bD1 = bD0 + 64 * 80;

    float acc[4][4][4];
    #pragma unroll
    for (int mt = 0; mt < 4; mt++)
        #pragma unroll
        for (int nt = 0; nt < 4; nt++)
            #pragma unroll
            for (int r = 0; r < 4; r++) acc[mt][nt][r] = 0.f;

    auto issue = [&](int cc) {
        const uint32_t st = (uint32_t)(cc & 3) * 10240u;
        const int p = cc / KPC;
        const int akoff = ((p == 1) ? KP : 0) + (cc - p * KPC) * 32 + c16 * 8;
        const long bk = (long)cc * 32;
        CP_ASYNC16(aD0 + st, aP0 + akoff);
        CP_ASYNC16(aD1 + st, aP1 + akoff);
        CP_ASYNC16(bD0 + st, bP0 + bk);
        CP_ASYNC16(bD1 + st, bP1 + bk);
        CP_COMMIT();
    };

    issue(0);
    if (NC > 1) issue(1);
    if (NC > 2) issue(2);

    const int gRow  = lane >> 2;
    const int cPair = (lane & 3) * 2;

    for (int c = 0; c < NC; c++) {
        if      (c + 2 < NC) CP_WAIT2();
        else if (c + 1 < NC) CP_WAIT1();
        else                 CP_WAIT0();
        __syncthreads();
        if (c + 3 < NC) issue(c + 3);

        const uint32_t st = (uint32_t)(c & 3) * 10240u;
        const uint32_t aW = smBase + st + (warpM * 64) * 80;
        const uint32_t bW = smBase + B_OFF + st + (warpN * 32) * 80;

        #pragma unroll
        for (int kh = 0; kh < 2; kh++) {
            uint32_t a[4][4], bf_[2][4];
            const uint32_t lrow = (lane & 15) * 80;
            const uint32_t lcol = kh * 32 + (lane >> 4) * 16;
            #pragma unroll
            for (int mt = 0; mt < 4; mt++)
                LDMX4(a[mt][0], a[mt][1], a[mt][2], a[mt][3],
                      aW + (mt * 16) * 80 + lrow + lcol);
            #pragma unroll
            for (int g = 0; g < 2; g++)
                LDMX4(bf_[g][0], bf_[g][1], bf_[g][2], bf_[g][3],
                      bW + (g * 16) * 80 + lrow + lcol);
            #pragma unroll
            for (int mt = 0; mt < 4; mt++)
                #pragma unroll
                for (int nt = 0; nt < 4; nt++)
                    MMA16816(acc[mt][nt], a[mt], bf_[nt >> 1][nt & 1], bf_[nt >> 1][(nt & 1) + 2]);
        }
    }
    __syncthreads();

    // ---- epilogue ----
    #pragma unroll
    for (int mt = 0; mt < 4; mt++) {
        #pragma unroll
        for (int nt = 0; nt < 4; nt++) {
            const int n = n0 + warpN * 32 + nt * 8 + cPair;
            if (n >= Nreal) continue;
            const float b0 = bias[n], b1 = bias[n + 1];
            #pragma unroll
            for (int h = 0; h < 2; h++) {
                const long m = m0 + warpM * 64 + mt * 16 + h * 8 + gRow;
                if (STAGE == 5) {
                    float v0 = fmaf(-2.f, acc[mt][nt][h * 2 + 0], b0);
                    float v1 = fmaf(-2.f, acc[mt][nt][h * 2 + 1], b1);
                    *(float2*)(outF + m * outFs + n) = make_float2(v0, v1);
                    continue;
                }
                float v0 = acc[mt][nt][h * 2 + 0] + b0;
                float v1 = acc[mt][nt][h * 2 + 1] + b1;
                if (STAGE == 0) { v0 = fmaxf(v0, 0.f); v1 = fmaxf(v1, 0.f); }
                if (STAGE == 4) {
                    float s0 = 1.f / (1.f + __expf(-v0));
                    float s1 = 1.f / (1.f + __expf(-v1));
                    *(float2*)(outF + m * outFs + n) = make_float2(s0, s1);
                } else {
                    bf16 t00 = __float2bfloat16(v0);
                    bf16 t01 = __float2bfloat16(v1);
                    float r0 = v0 - __bfloat162float(t00);
                    float r1 = v1 - __bfloat162float(t01);
                    bf16* d = outE + m * (long)outRow + n;
                    *(__nv_bfloat162*)(d)         = __nv_bfloat162(t00, t01);
                    *(__nv_bfloat162*)(d + outKP) =
                        __nv_bfloat162(__float2bfloat16(r0), __float2bfloat16(r1));
                }
            }
        }
    }
}

// ===========================================================================
// Launch
// ===========================================================================
extern "C" void kernel_launch(void* const* d_in, const int* in_sizes, int n_in,
                              void* d_out, int out_size) {
    const float* x   = (const float*)d_in[0];
    const float* W1  = (const float*)d_in[1];
    const float* b1  = (const float*)d_in[2];
    const float* W2  = (const float*)d_in[3];
    const float* b2  = (const float*)d_in[4];
    const float* W3  = (const float*)d_in[5];
    const float* b3  = (const float*)d_in[6];
    const float* W4  = (const float*)d_in[7];
    const float* b4  = (const float*)d_in[8];
    const float* emb = (const float*)d_in[9];
    float* out = (float*)d_out;

    bf16 *xext, *h1e, *zee, *h3e, *w1e, *w2e, *w3e, *w4e, *embvq, *embdec;
    float *en, *Dm; int *idx;
    cudaGetSymbolAddress((void**)&xext,   g_xext);
    cudaGetSymbolAddress((void**)&h1e,    g_h1e);
    cudaGetSymbolAddress((void**)&zee,    g_zee);
    cudaGetSymbolAddress((void**)&h3e,    g_h3e);
    cudaGetSymbolAddress((void**)&w1e,    g_w1e);
    cudaGetSymbolAddress((void**)&w2e,    g_w2e);
    cudaGetSymbolAddress((void**)&w3e,    g_w3e);
    cudaGetSymbolAddress((void**)&w4e,    g_w4e);
    cudaGetSymbolAddress((void**)&embvq,  g_embvq);
    cudaGetSymbolAddress((void**)&embdec, g_embdec);
    cudaGetSymbolAddress((void**)&en,     g_en);
    cudaGetSymbolAddress((void**)&Dm,     g_D);
    cudaGetSymbolAddress((void**)&idx,    g_idx);

    const int SMEM = NSTG * STGB;  // 81920
    cudaFuncSetAttribute(hgemm<0, false>, cudaFuncAttributeMaxDynamicSharedMemorySize, SMEM);
    cudaFuncSetAttribute(hgemm<1, false>, cudaFuncAttributeMaxDynamicSharedMemorySize, SMEM);
    cudaFuncSetAttribute(hgemm<5, false>, cudaFuncAttributeMaxDynamicSharedMemorySize, SMEM);
    cudaFuncSetAttribute(hgemm<0, true >, cudaFuncAttributeMaxDynamicSharedMemorySize, SMEM);
    cudaFuncSetAttribute(hgemm<4, false>, cudaFuncAttributeMaxDynamicSharedMemorySize, SMEM);

    // ---- prep ----
    enorm_kernel<<<EMBED_NUM / 8, 256>>>(emb, en);
    conv_A<<<4096, 256>>>(x,   xext,   (long)BZ, INPUT_DIM);
    conv_A<<<512,  256>>>(emb, embdec, (long)EMBED_NUM, EMBED_DIM);
    conv_B<<<2048, 256>>>(W1,  w1e,   HIDDEN,    512,  INPUT_DIM, 1024);
    conv_B<<<512,  256>>>(W2,  w2e,   EMBED_DIM, 256,  HIDDEN,    416);
    conv_B<<<512,  256>>>(emb, embvq, EMBED_NUM, 2048, EMBED_DIM, 256);
    conv_B<<<512,  256>>>(W3,  w3e,   HIDDEN,    512,  EMBED_DIM, 256);
    conv_B<<<1024, 256>>>(W4,  w4e,   INPUT_DIM, 1024, HIDDEN,    416);
    zero_pad<<<512, 256>>>(h1e, BZ, HIDDEN, 416);
    zero_pad<<<512, 256>>>(h3e, BZ, HIDDEN, 416);

    // ---- G1: h1 = relu(x @ W1^T + b1), 3-product ----
    hgemm<0, false><<<dim3(128, 4), 256, SMEM>>>(
        xext, 2048, 1024, 32, 96, w1e, 3072, b1, HIDDEN, nullptr,
        h1e, 832, 416, nullptr, 0);

    // ---- G2: z_e = h1 @ W2^T + b2, 3-product ----
    hgemm<1, false><<<dim3(128, 2), 256, SMEM>>>(
        h1e, 832, 416, 13, 39, w2e, 1248, b2, EMBED_DIM, nullptr,
        zee, 512, 256, nullptr, 0);

    // ---- VQ prefilter: approx distances, 1-product (z0 . e0) ----
    hgemm<5, false><<<dim3(128, 16), 256, SMEM>>>(
        zee, 512, 256, 8, 8, embvq, 768, en, EMBED_NUM, nullptr,
        nullptr, 0, 0, Dm, EMBED_NUM);

    // ---- VQ exact refine: min + candidates within DELTA + exact distances ----
    scan_refine<<<BZ / 8, 256>>>(Dm, zee, emb, idx);

    // ---- G3: h3 = relu(emb[idx] @ W3^T + b3), gather fused, 3-product ----
    hgemm<0, true><<<dim3(128, 4), 256, SMEM>>>(
        embdec, 512, 256, 8, 24, w3e, 768, b3, HIDDEN, idx,
        h3e, 832, 416, nullptr, 0);

    // ---- G4: out = sigmoid(h3 @ W4^T + b4), 2-product ----
    hgemm<4, false><<<dim3(128, 8), 256, SMEM>>>(
        h3e, 832, 416, 13, 26, w4e, 1248, b4, INPUT_DIM, nullptr,
        nullptr, 0, 0, out, INPUT_DIM);
}

// round 8
// speedup vs baseline: 2.8904x; 1.5060x over previous
#include <cuda_runtime.h>
#include <cuda_bf16.h>
#include <cuda_fp16.h>
#include <cstdint>

typedef __nv_bfloat16 bf16;

#define BZ        16384
#define INPUT_DIM 1024
#define HIDDEN    400
#define EMBED_DIM 256
#define EMBED_NUM 2048

// ===========================================================================
// Scratch (allocation-free __device__ globals)
// Encoder (bf16 3-product): A-ext [m][2*KP] blocks [a0|a1];
//                           B-ext [n][3*KP] blocks [b0|b0|b1]
// Decoder (fp16 1-product): plain fp16 operands.
// ===========================================================================
__device__ __align__(16) bf16   g_xext [16384L * 2048];  // KP=1024
__device__ __align__(16) bf16   g_h1e  [16384L * 832];   // KP=416
__device__ __align__(16) bf16   g_zee  [16384L * 512];   // KP=256
__device__ __align__(16) bf16   g_w1e  [512L   * 3072];  // N 400->512
__device__ __align__(16) bf16   g_w2e  [256L   * 1248];  // KP=416
__device__ __align__(16) bf16   g_embq [2048L  * 256];   // bf16(emb), VQ prefilter B
__device__ __align__(16) __half g_embh [2048L  * 256];   // fp16(emb), G3 A (gathered)
__device__ __align__(16) __half g_w3h  [512L   * 256];   // N 400->512
__device__ __align__(16) __half g_h3h  [16384L * 416];   // KP=416
__device__ __align__(16) __half g_w4h  [1024L  * 416];   // K 400->416
__device__ __align__(16) __half g_Dh   [16384L * 2048];  // approx VQ distances
__device__ float g_en[EMBED_NUM];
__device__ int   g_idx[BZ];

// ===========================================================================
// PTX helpers
// ===========================================================================
__device__ __forceinline__ uint32_t smem_u32(const void* p) {
    uint32_t a;
    asm("{ .reg .u64 t; cvta.to.shared.u64 t, %1; cvt.u32.u64 %0, t; }"
        : "=r"(a) : "l"(p));
    return a;
}

#define CP_ASYNC16(dst, src) \
    asm volatile("cp.async.cg.shared.global [%0], [%1], 16;" :: "r"(dst), "l"(src) : "memory")
#define CP_COMMIT() asm volatile("cp.async.commit_group;" ::: "memory")
#define CP_WAIT2()  asm volatile("cp.async.wait_group 2;" ::: "memory")
#define CP_WAIT1()  asm volatile("cp.async.wait_group 1;" ::: "memory")
#define CP_WAIT0()  asm volatile("cp.async.wait_group 0;" ::: "memory")

#define LDMX4(r0, r1, r2, r3, addr) \
    asm volatile("ldmatrix.sync.aligned.m8n8.x4.shared.b16 {%0,%1,%2,%3}, [%4];" \
        : "=r"(r0), "=r"(r1), "=r"(r2), "=r"(r3) : "r"(addr))

template <typename T> struct MmaSel;
template <> struct MmaSel<bf16> {
    static __device__ __forceinline__ void run(float* d, const uint32_t* a,
                                               uint32_t b0, uint32_t b1) {
        asm volatile("mma.sync.aligned.m16n8k16.row.col.f32.bf16.bf16.f32 "
            "{%0,%1,%2,%3}, {%4,%5,%6,%7}, {%8,%9}, {%0,%1,%2,%3};"
            : "+f"(d[0]), "+f"(d[1]), "+f"(d[2]), "+f"(d[3])
            : "r"(a[0]), "r"(a[1]), "r"(a[2]), "r"(a[3]), "r"(b0), "r"(b1));
    }
};
template <> struct MmaSel<__half> {
    static __device__ __forceinline__ void run(float* d, const uint32_t* a,
                                               uint32_t b0, uint32_t b1) {
        asm volatile("mma.sync.aligned.m16n8k16.row.col.f32.f16.f16.f32 "
            "{%0,%1,%2,%3}, {%4,%5,%6,%7}, {%8,%9}, {%0,%1,%2,%3};"
            : "+f"(d[0]), "+f"(d[1]), "+f"(d[2]), "+f"(d[3])
            : "r"(a[0]), "r"(a[1]), "r"(a[2]), "r"(a[3]), "r"(b0), "r"(b1));
    }
};

// ===========================================================================
// Prep kernels
// ===========================================================================
__global__ void enorm_kernel(const float* __restrict__ E, float* __restrict__ en) {
    int j    = blockIdx.x * 8 + (threadIdx.x >> 5);
    int lane = threadIdx.x & 31;
    const float* row = E + (long)j * EMBED_DIM;
    float s = 0.f;
    for (int k = lane; k < EMBED_DIM; k += 32) { float v = row[k]; s += v * v; }
    #pragma unroll
    for (int o = 16; o; o >>= 1) s += __shfl_xor_sync(0xFFFFFFFFu, s, o);
    if (lane == 0) en[j] = s;
}

// A-side bf16 2-term split (K == KP)
__global__ void conv_A(const float* __restrict__ in, bf16* __restrict__ out,
                       long rows, int K) {
    long tot = rows * K;
    for (long i = blockIdx.x * 256L + threadIdx.x; i < tot; i += gridDim.x * 256L) {
        long m = i / K;
        int  k = (int)(i - m * K);
        float v = in[i];
        bf16 t0 = __float2bfloat16(v);
        float r = v - __bfloat162float(t0);
        bf16* o = out + m * (2L * K) + k;
        o[0] = t0; o[K] = __float2bfloat16(r);
    }
}

// B-side bf16: blocks [b0|b0|b1]; zero-pads n>=N, k>=K
__global__ void conv_B(const float* __restrict__ W, bf16* __restrict__ out,
                       int N, int Npad, int K, int KP) {
    long tot = (long)Npad * KP;
    for (long i = blockIdx.x * 256L + threadIdx.x; i < tot; i += gridDim.x * 256L) {
        int n = (int)(i / KP);
        int k = (int)(i - (long)n * KP);
        float v = (n < N && k < K) ? W[(long)n * K + k] : 0.f;
        bf16 s0 = __float2bfloat16(v);
        float r = v - __bfloat162float(s0);
        bf16* o = out + (long)n * (3L * KP) + k;
        o[0] = s0; o[KP] = s0; o[2L * KP] = __float2bfloat16(r);
    }
}

// plain fp16 weight conversion with pad
__global__ void conv_Bh(const float* __restrict__ W, __half* __restrict__ out,
                        int N, int Npad, int K, int KP) {
    long tot = (long)Npad * KP;
    for (long i = blockIdx.x * 256L + threadIdx.x; i < tot; i += gridDim.x * 256L) {
        int n = (int)(i / KP);
        int k = (int)(i - (long)n * KP);
        float v = (n < N && k < K) ? W[(long)n * K + k] : 0.f;
        out[i] = __float2half_rn(v);
    }
}

__global__ void f2bf(const float* __restrict__ in, bf16* __restrict__ out, long tot) {
    for (long i = blockIdx.x * 256L + threadIdx.x; i < tot; i += gridDim.x * 256L)
        out[i] = __float2bfloat16(in[i]);
}
__global__ void f2h(const float* __restrict__ in, __half* __restrict__ out, long tot) {
    for (long i = blockIdx.x * 256L + threadIdx.x; i < tot; i += gridDim.x * 256L)
        out[i] = __float2half_rn(in[i]);
}

__global__ void zero_pad(bf16* __restrict__ buf, long rows, int K, int KP) {
    int pad = KP - K;
    long tot = rows * 2L * pad;
    bf16 z = __float2bfloat16(0.f);
    for (long i = blockIdx.x * 256L + threadIdx.x; i < tot; i += gridDim.x * 256L) {
        long m = i / (2 * pad);
        int rem = (int)(i - m * (2 * pad));
        int s = rem / pad, k = K + (rem - (rem / pad) * pad);
        buf[m * (2L * KP) + (long)s * KP + k] = z;
    }
}
__global__ void zero_pad_h(__half* __restrict__ buf, long rows, int K, int KP) {
    int pad = KP - K;
    long tot = rows * pad;
    __half z = __float2half_rn(0.f);
    for (long i = blockIdx.x * 256L + threadIdx.x; i < tot; i += gridDim.x * 256L) {
        long m = i / pad;
        int k = K + (int)(i - m * pad);
        buf[m * (long)KP + k] = z;
    }
}

// ===========================================================================
// VQ scan + exact refine (D in fp16)
// ===========================================================================
#define VQ_DELTA 0.8f

__global__ __launch_bounds__(256)
void scan_refine(const __half* __restrict__ D, const bf16* __restrict__ zee,
                 const float* __restrict__ emb, int* __restrict__ idx) {
    const int wid = threadIdx.x >> 5, lane = threadIdx.x & 31;
    const long row = blockIdx.x * 8 + wid;
    const __half2* d2 = (const __half2*)(D + row * EMBED_NUM);

    float mn = 3.4e38f;
    for (int k = lane; k < EMBED_NUM / 2; k += 32) {
        float2 v = __half22float2(d2[k]);
        mn = fminf(mn, fminf(v.x, v.y));
    }
    #pragma unroll
    for (int o = 16; o; o >>= 1) mn = fminf(mn, __shfl_xor_sync(0xFFFFFFFFu, mn, o));
    const float thr = mn + VQ_DELTA;

    __shared__ int cnt[8];
    __shared__ int cand[8][32];
    if (lane == 0) cnt[wid] = 0;
    __syncwarp();
    for (int k = lane; k < EMBED_NUM / 2; k += 32) {
        float2 v = __half22float2(d2[k]);
        if (v.x <= thr) { int p = atomicAdd(&cnt[wid], 1); if (p < 32) cand[wid][p] = 2 * k; }
        if (v.y <= thr) { int p = atomicAdd(&cnt[wid], 1); if (p < 32) cand[wid][p] = 2 * k + 1; }
    }
    __syncwarp();
    const int nc = min(cnt[wid], 32);

    float z[8];
    #pragma unroll
    for (int t = 0; t < 8; t++) {
        int k = lane + t * 32;
        z[t] = __bfloat162float(zee[row * 512 + k])
             + __bfloat162float(zee[row * 512 + 256 + k]);
    }

    float bd = 3.4e38f; int bi = 0x7FFFFFFF;
    for (int c = 0; c < nc; c++) {
        const int j = cand[wid][c];
        const float* e = emb + (long)j * EMBED_DIM;
        float s = 0.f;
        #pragma unroll
        for (int t = 0; t < 8; t++) {
            float df = z[t] - e[lane + t * 32];
            s = fmaf(df, df, s);
        }
        #pragma unroll
        for (int o = 16; o; o >>= 1) s += __shfl_xor_sync(0xFFFFFFFFu, s, o);
        if (s < bd || (s == bd && j < bi)) { bd = s; bi = j; }
    }
    if (lane == 0) idx[row] = bi;
}

// ===========================================================================
// HMMA GEMM: BM=128, BN=128, BK=32, 4-stage cp.async pipeline, 256 thr.
// STAGE: 0 = relu + bf16 split store, 1 = bf16 split store,
//        4 = sigmoid fp32 store, 5 = VQ approx D (fp16), 6 = relu fp16 store.
// ===========================================================================
#define NSTG   4
#define B_OFF  (NSTG * 10240)

template <int STAGE, bool GATHER, typename T>
__global__ __launch_bounds__(256, 2)
void hgemm(const T* __restrict__ A, int Arow, int KP, int KPC, int NC,
           const T* __restrict__ B, int Brow,
           const float* __restrict__ bias, int Nreal,
           const int* __restrict__ gidx,
           bf16* __restrict__ outE, int outRow, int outKP,
           float* __restrict__ outF,
           __half* __restrict__ outH, int outS) {
    extern __shared__ __align__(16) char smem[];
    const uint32_t smBase = smem_u32(smem);
    const int tid  = threadIdx.x;
    const int lane = tid & 31, wid = tid >> 5;
    const int warpM = wid >> 2, warpN = wid & 3;
    const int m0 = blockIdx.x * 128;
    const int n0 = blockIdx.y * 128;

    const int r4  = tid >> 2;
    const int c16 = tid & 3;
    long gr0 = GATHER ? (long)gidx[m0 + r4]      : (long)(m0 + r4);
    long gr1 = GATHER ? (long)gidx[m0 + 64 + r4] : (long)(m0 + 64 + r4);
    const T* aP0 = A + gr0 * (long)Arow;
    const T* aP1 = A + gr1 * (long)Arow;
    const T* bP0 = B + (long)(n0 + r4) * Brow + c16 * 8;
    const T* bP1 = B + (long)(n0 + 64 + r4) * Brow + c16 * 8;
    const uint32_t aD0 = smBase + r4 * 80 + c16 * 16;
    const uint32_t aD1 = aD0 + 64 * 80;
    const uint32_t bD0 = smBase + B_OFF + r4 * 80 + c16 * 16;
    const uint32_t bD1 = bD0 + 64 * 80;

    float acc[4][4][4];
    #pragma unroll
    for (int mt = 0; mt < 4; mt++)
        #pragma unroll
        for (int nt = 0; nt < 4; nt++)
            #pragma unroll
            for (int r = 0; r < 4; r++) acc[mt][nt][r] = 0.f;

    auto issue = [&](int cc) {
        const uint32_t st = (uint32_t)(cc & 3) * 10240u;
        const int p = cc / KPC;
        const int akoff = ((p == 1) ? KP : 0) + (cc - p * KPC) * 32 + c16 * 8;
        const long bk = (long)cc * 32;
        CP_ASYNC16(aD0 + st, aP0 + akoff);
        CP_ASYNC16(aD1 + st, aP1 + akoff);
        CP_ASYNC16(bD0 + st, bP0 + bk);
        CP_ASYNC16(bD1 + st, bP1 + bk);
        CP_COMMIT();
    };

    issue(0);
    if (NC > 1) issue(1);
    if (NC > 2) issue(2);

    const int gRow  = lane >> 2;
    const int cPair = (lane & 3) * 2;

    for (int c = 0; c < NC; c++) {
        if      (c + 2 < NC) CP_WAIT2();
        else if (c + 1 < NC) CP_WAIT1();
        else                 CP_WAIT0();
        __syncthreads();
        if (c + 3 < NC) issue(c + 3);

        const uint32_t st = (uint32_t)(c & 3) * 10240u;
        const uint32_t aW = smBase + st + (warpM * 64) * 80;
        const uint32_t bW = smBase + B_OFF + st + (warpN * 32) * 80;

        #pragma unroll
        for (int kh = 0; kh < 2; kh++) {
            uint32_t a[4][4], bf_[2][4];
            const uint32_t lrow = (lane & 15) * 80;
            const uint32_t lcol = kh * 32 + (lane >> 4) * 16;
            #pragma unroll
            for (int mt = 0; mt < 4; mt++)
                LDMX4(a[mt][0], a[mt][1], a[mt][2], a[mt][3],
                      aW + (mt * 16) * 80 + lrow + lcol);
            #pragma unroll
            for (int g = 0; g < 2; g++)
                LDMX4(bf_[g][0], bf_[g][1], bf_[g][2], bf_[g][3],
                      bW + (g * 16) * 80 + lrow + lcol);
            #pragma unroll
            for (int mt = 0; mt < 4; mt++)
                #pragma unroll
                for (int nt = 0; nt < 4; nt++)
                    MmaSel<T>::run(acc[mt][nt], a[mt],
                                   bf_[nt >> 1][nt & 1], bf_[nt >> 1][(nt & 1) + 2]);
        }
    }
    __syncthreads();

    // ---- epilogue ----
    #pragma unroll
    for (int mt = 0; mt < 4; mt++) {
        #pragma unroll
        for (int nt = 0; nt < 4; nt++) {
            const int n = n0 + warpN * 32 + nt * 8 + cPair;
            if (n >= Nreal) continue;
            const float b0 = bias[n], b1 = bias[n + 1];
            #pragma unroll
            for (int h = 0; h < 2; h++) {
                const long m = m0 + warpM * 64 + mt * 16 + h * 8 + gRow;
                if (STAGE == 5) {
                    float v0 = fmaf(-2.f, acc[mt][nt][h * 2 + 0], b0);
                    float v1 = fmaf(-2.f, acc[mt][nt][h * 2 + 1], b1);
                    *(__half2*)(outH + m * (long)outS + n) = __floats2half2_rn(v0, v1);
                    continue;
                }
                float v0 = acc[mt][nt][h * 2 + 0] + b0;
                float v1 = acc[mt][nt][h * 2 + 1] + b1;
                if (STAGE == 0 || STAGE == 6) { v0 = fmaxf(v0, 0.f); v1 = fmaxf(v1, 0.f); }
                if (STAGE == 4) {
                    float s0 = 1.f / (1.f + __expf(-v0));
                    float s1 = 1.f / (1.f + __expf(-v1));
                    *(float2*)(outF + m * (long)outS + n) = make_float2(s0, s1);
                } else if (STAGE == 6) {
                    *(__half2*)(outH + m * (long)outS + n) = __floats2half2_rn(v0, v1);
                } else {
                    bf16 t00 = __float2bfloat16(v0);
                    bf16 t01 = __float2bfloat16(v1);
                    float r0 = v0 - __bfloat162float(t00);
                    float r1 = v1 - __bfloat162float(t01);
                    bf16* d = outE + m * (long)outRow + n;
                    *(__nv_bfloat162*)(d)         = __nv_bfloat162(t00, t01);
                    *(__nv_bfloat162*)(d + outKP) =
                        __nv_bfloat162(__float2bfloat16(r0), __float2bfloat16(r1));
                }
            }
        }
    }
}

// ===========================================================================
// Launch
// ===========================================================================
extern "C" void kernel_launch(void* const* d_in, const int* in_sizes, int n_in,
                              void* d_out, int out_size) {
    const float* x   = (const float*)d_in[0];
    const float* W1  = (const float*)d_in[1];
    const float* b1  = (const float*)d_in[2];
    const float* W2  = (const float*)d_in[3];
    const float* b2  = (const float*)d_in[4];
    const float* W3  = (const float*)d_in[5];
    const float* b3  = (const float*)d_in[6];
    const float* W4  = (const float*)d_in[7];
    const float* b4  = (const float*)d_in[8];
    const float* emb = (const float*)d_in[9];
    float* out = (float*)d_out;

    bf16 *xext, *h1e, *zee, *w1e, *w2e, *embq;
    __half *embh, *w3h, *h3h, *w4h, *Dh;
    float *en; int *idx;
    cudaGetSymbolAddress((void**)&xext, g_xext);
    cudaGetSymbolAddress((void**)&h1e,  g_h1e);
    cudaGetSymbolAddress((void**)&zee,  g_zee);
    cudaGetSymbolAddress((void**)&w1e,  g_w1e);
    cudaGetSymbolAddress((void**)&w2e,  g_w2e);
    cudaGetSymbolAddress((void**)&embq, g_embq);
    cudaGetSymbolAddress((void**)&embh, g_embh);
    cudaGetSymbolAddress((void**)&w3h,  g_w3h);
    cudaGetSymbolAddress((void**)&h3h,  g_h3h);
    cudaGetSymbolAddress((void**)&w4h,  g_w4h);
    cudaGetSymbolAddress((void**)&Dh,   g_Dh);
    cudaGetSymbolAddress((void**)&en,   g_en);
    cudaGetSymbolAddress((void**)&idx,  g_idx);

    const int SMEM = NSTG * 20480;  // 81920
    cudaFuncSetAttribute(hgemm<0, false, bf16>,   cudaFuncAttributeMaxDynamicSharedMemorySize, SMEM);
    cudaFuncSetAttribute(hgemm<1, false, bf16>,   cudaFuncAttributeMaxDynamicSharedMemorySize, SMEM);
    cudaFuncSetAttribute(hgemm<5, false, bf16>,   cudaFuncAttributeMaxDynamicSharedMemorySize, SMEM);
    cudaFuncSetAttribute(hgemm<6, true,  __half>, cudaFuncAttributeMaxDynamicSharedMemorySize, SMEM);
    cudaFuncSetAttribute(hgemm<4, false, __half>, cudaFuncAttributeMaxDynamicSharedMemorySize, SMEM);

    // ---- prep ----
    enorm_kernel<<<EMBED_NUM / 8, 256>>>(emb, en);
    conv_A<<<4096, 256>>>(x, xext, (long)BZ, INPUT_DIM);
    conv_B<<<2048, 256>>>(W1, w1e, HIDDEN, 512, INPUT_DIM, 1024);
    conv_B<<<512,  256>>>(W2, w2e, EMBED_DIM, 256, HIDDEN, 416);
    f2bf<<<512, 256>>>(emb, embq, (long)EMBED_NUM * EMBED_DIM);
    f2h <<<512, 256>>>(emb, embh, (long)EMBED_NUM * EMBED_DIM);
    conv_Bh<<<256, 256>>>(W3, w3h, HIDDEN, 512, EMBED_DIM, 256);
    conv_Bh<<<512, 256>>>(W4, w4h, INPUT_DIM, 1024, HIDDEN, 416);
    zero_pad<<<512, 256>>>(h1e, BZ, HIDDEN, 416);
    zero_pad_h<<<512, 256>>>(h3h, BZ, HIDDEN, 416);

    // ---- G1: h1 = relu(x @ W1^T + b1), bf16 3-product ----
    hgemm<0, false, bf16><<<dim3(128, 4), 256, SMEM>>>(
        xext, 2048, 1024, 32, 96, w1e, 3072, b1, HIDDEN, nullptr,
        h1e, 832, 416, nullptr, nullptr, 0);

    // ---- G2: z_e = h1 @ W2^T + b2, bf16 3-product ----
    hgemm<1, false, bf16><<<dim3(128, 2), 256, SMEM>>>(
        h1e, 832, 416, 13, 39, w2e, 1248, b2, EMBED_DIM, nullptr,
        zee, 512, 256, nullptr, nullptr, 0);

    // ---- VQ prefilter: approx D (fp16 store), bf16 1-product ----
    hgemm<5, false, bf16><<<dim3(128, 16), 256, SMEM>>>(
        zee, 512, 256, 8, 8, embq, 256, en, EMBED_NUM, nullptr,
        nullptr, 0, 0, nullptr, Dh, EMBED_NUM);

    // ---- VQ exact refine ----
    scan_refine<<<BZ / 8, 256>>>(Dh, zee, emb, idx);

    // ---- G3: h3 = relu(emb[idx] @ W3^T + b3), fp16 1-product, gather ----
    hgemm<6, true, __half><<<dim3(128, 4), 256, SMEM>>>(
        embh, 256, 256, 8, 8, w3h, 256, b3, HIDDEN, idx,
        nullptr, 0, 0, nullptr, h3h, 416);

    // ---- G4: out = sigmoid(h3 @ W4^T + b4), fp16 1-product ----
    hgemm<4, false, __half><<<dim3(128, 8), 256, SMEM>>>(
        h3h, 416, 416, 13, 13, w4h, 416, b4, INPUT_DIM, nullptr,
        nullptr, 0, 0, out, nullptr, INPUT_DIM);
}